// round 14
// baseline (speedup 1.0000x reference)
#include <cuda_runtime.h>
#include <cuda_fp16.h>
#include <cstdint>
#include <math.h>

// ---------------- scratch (device globals; no allocation) ----------------
__device__ float g_lat[5570560];        // 4 levels of raw laterals (256,H,W)
__device__ uint32_t g_lath[2785280];    // packed half2 combined lat (ic-pair, HW)
__device__ uint32_t g_wt[1179648];      // fp16 conv weights, fragment order
__device__ uint32_t g_lwh[491520];      // fp16 lateral weights, fragment order
__device__ uint32_t g_xh[3932160];      // packed half2 x inputs (k-pair, HW)
__device__ uint32_t g_T[25067520];      // per-tap GEMM outputs T_j, half2 px pairs
__device__ uint32_t g_feash[13926400];  // feas as half2 (px pairs)
__device__ float g_part[3670016];       // split-K partials (all levels)
__device__ float g_fsum[4 * 256];
__device__ float g_att[4 * 5 * 256];

#define BN_EPS 1e-5f

__device__ __forceinline__ uint32_t smem_u32(const void* p) {
    uint32_t a;
    asm("{ .reg .u64 t; cvta.to.shared.u64 t, %1; cvt.u32.u64 %0, t; }" : "=r"(a) : "l"(p));
    return a;
}
#define CP_ASYNC16(dst, src) \
    asm volatile("cp.async.cg.shared.global [%0], [%1], 16;" \
                 :: "r"(dst), "l"(src) : "memory")
#define CP_COMMIT() asm volatile("cp.async.commit_group;" ::: "memory")
#define CP_WAIT0()  asm volatile("cp.async.wait_group 0;" ::: "memory")

__device__ __forceinline__ void mma16h(float* c, const uint32_t* a,
                                       uint32_t b0, uint32_t b1) {
    asm volatile(
        "mma.sync.aligned.m16n8k16.row.col.f32.f16.f16.f32 "
        "{%0,%1,%2,%3}, {%4,%5,%6,%7}, {%8,%9}, {%0,%1,%2,%3};"
        : "+f"(c[0]), "+f"(c[1]), "+f"(c[2]), "+f"(c[3])
        : "r"(a[0]), "r"(a[1]), "r"(a[2]), "r"(a[3]), "r"(b0), "r"(b1));
}
__device__ __forceinline__ uint32_t packh2(float a, float b) {
    uint32_t h0 = __half_as_ushort(__float2half_rn(a));
    uint32_t h1 = __half_as_ushort(__float2half_rn(b));
    return (h1 << 16) | h0;
}

// ---------------- fused prep: conv wt + lateral wt + x convert ------------
// grid segments: [0,4608) wt_transpose | [4608,6528) wt_lat | [6528,10368) cvt_x
__global__ void prep_all(const float* __restrict__ aacw,
                         const float* __restrict__ lw0, const float* __restrict__ lw1,
                         const float* __restrict__ lw2, const float* __restrict__ lw3,
                         const float* __restrict__ x0, const float* __restrict__ x1,
                         const float* __restrict__ x2, const float* __restrict__ x3)
{
    const int bx = blockIdx.x;
    const int tid = threadIdx.x;
    if (bx < 4608) {
        // ---- conv weight transpose to fp16 fragment order (+ zero fsum) ----
        if (bx == 0) {
            for (int k = tid; k < 1024; k += 256) g_fsum[k] = 0.f;
        }
        int idx = bx * 256 + tid;
        if (idx >= 1179648) return;
        int q = idx & 3;
        int l = (idx >> 2) & 31;
        int t = (idx >> 7) & 15;
        int kc = (idx >> 11) & 15;
        int lj = idx >> 15;           // lvl*9 + j
        int j = lj % 9, lvl = lj / 9;
        int oc = t * 16 + (l >> 2) + 8 * (q & 1);
        int pair = kc * 8 + (l & 3) + 4 * (q >> 1);
        float w0 = aacw[((lvl * 256 + oc) * 256 + 2 * pair) * 9 + j];
        float w1 = aacw[((lvl * 256 + oc) * 256 + 2 * pair + 1) * 9 + j];
        g_wt[idx] = packh2(w0, w1);
    } else if (bx < 6528) {
        // ---- lateral weight transpose, all levels ----
        int idx = (bx - 4608) * 256 + tid;
        int lvl, off, K;
        if (idx < 32768)       { lvl = 0; off = 0;      K = 256;  }
        else if (idx < 98304)  { lvl = 1; off = 32768;  K = 512;  }
        else if (idx < 229376) { lvl = 2; off = 98304;  K = 1024; }
        else                   { lvl = 3; off = 229376; K = 2048; }
        const float* lw = lvl == 0 ? lw0 : lvl == 1 ? lw1 : lvl == 2 ? lw2 : lw3;
        int i2 = idx - off;
        int q = i2 & 3;
        int l = (i2 >> 2) & 31;
        int t = (i2 >> 7) & 15;
        int kc = i2 >> 11;
        int oc = t * 16 + (l >> 2) + 8 * (q & 1);
        int pair = kc * 8 + (l & 3) + 4 * (q >> 1);
        g_lwh[idx] = packh2(lw[oc * K + 2 * pair], lw[oc * K + 2 * pair + 1]);
    } else {
        // ---- x -> packed half2, 4 pixels per thread (vectorized) ----
        int idx4 = (bx - 6528) * 256 + tid;  // 983040 total
        int lvl, off4, N;
        if (idx4 < 524288)      { lvl = 0; off4 = 0;      N = 16384; }
        else if (idx4 < 786432) { lvl = 1; off4 = 524288; N = 4096;  }
        else if (idx4 < 917504) { lvl = 2; off4 = 786432; N = 1024;  }
        else                    { lvl = 3; off4 = 917504; N = 256;   }
        const float* x = lvl == 0 ? x0 : lvl == 1 ? x1 : lvl == 2 ? x2 : x3;
        int i2 = (idx4 - off4) * 4;
        int p = i2 / N;
        int n = i2 - p * N;                 // multiple of 4
        const float4 a = *(const float4*)&x[(size_t)(2 * p) * N + n];
        const float4 b = *(const float4*)&x[(size_t)(2 * p + 1) * N + n];
        uint4 pk;
        pk.x = packh2(a.x, b.x);
        pk.y = packh2(a.y, b.y);
        pk.z = packh2(a.z, b.z);
        pk.w = packh2(a.w, b.w);
        *(uint4*)&g_xh[(size_t)idx4 * 4] = pk;
    }
}

// ---------------- lateral 1x1 conv, ALL levels + split-K in one grid ------
__global__ __launch_bounds__(256, 2)
void lat_mma_all(const float* __restrict__ lb)
{
    constexpr int SEG[4]   = {0, 128, 192, 224};
    constexpr int NB[4]    = {128, 32, 8, 2};
    constexpr int NS[4]    = {16384, 4096, 1024, 256};
    constexpr int LWOFF[4] = {0, 32768, 98304, 229376};
    constexpr int XOFF[4]  = {0, 2097152, 3145728, 3670016};
    constexpr int POFF[4]  = {0, 0, 2097152, 3145728};

    __shared__ uint32_t sB[2][16 * 136];
    const int tid = threadIdx.x;
    const int wid = tid >> 5, lid = tid & 31;
    const int g = lid >> 2, tig = lid & 3;
    const int warp_m = wid & 3, warp_n = wid >> 2;

    const int bx = blockIdx.x;
    const int lvl = bx >= SEG[3] ? 3 : bx >= SEG[2] ? 2 : bx >= SEG[1] ? 1 : 0;
    const int sub = bx - SEG[lvl];
    const int nb = sub & (NB[lvl] - 1);
    const int z = sub / NB[lvl];
    const int N = NS[lvl];
    const int n0 = nb * 128;
    const int my = blockIdx.y;

    const uint32_t* xh = g_xh + XOFF[lvl];
    const uint4* lw4 = (const uint4*)(g_lwh + LWOFF[lvl]);
    const uint32_t sbase = smem_u32(&sB[0][0]);
    const bool addb = (lvl == 0);
    float* out = addb ? g_lat : (g_part + POFF[lvl] + (size_t)z * 256 * N);

    float c[2][8][4];
#pragma unroll
    for (int mt = 0; mt < 2; mt++)
#pragma unroll
        for (int nt = 0; nt < 8; nt++)
#pragma unroll
            for (int q = 0; q < 4; q++) c[mt][nt][q] = 0.f;

    auto fill = [&](int ch, int b) {
        const int p0 = z * 128 + ch * 16;
#pragma unroll
        for (int e = tid; e < 512; e += 256) {
            int row = e >> 5, cw = e & 31;
            const uint32_t* src = xh + (size_t)(p0 + row) * N + n0 + cw * 4;
            uint32_t dst = sbase + (uint32_t)(b * 2176 + row * 136 + cw * 4) * 4u;
            CP_ASYNC16(dst, src);
        }
    };

    fill(0, 0);
    CP_COMMIT();
    CP_WAIT0();
    __syncthreads();

    for (int ch = 0; ch < 8; ch++) {
        const int cur = ch & 1;
        if (ch < 7) {
            fill(ch + 1, cur ^ 1);
            CP_COMMIT();
        }
        const uint32_t* s = &sB[cur][0];
#pragma unroll
        for (int ks = 0; ks < 2; ks++) {
            const int kc = z * 16 + ch * 2 + ks;
            uint32_t a[2][4];
#pragma unroll
            for (int mt = 0; mt < 2; mt++) {
                int t = my * 8 + warp_m * 2 + mt;
                uint4 av = lw4[(kc * 16 + t) * 32 + lid];
                a[mt][0] = av.x; a[mt][1] = av.y;
                a[mt][2] = av.z; a[mt][3] = av.w;
            }
            const int base_lo = (ks * 8 + tig) * 136;
            const int base_hi = base_lo + 4 * 136;
#pragma unroll
            for (int nt = 0; nt < 8; nt++) {
                int n = warp_n * 64 + nt * 8 + g;
                mma16h(c[0][nt], a[0], s[base_lo + n], s[base_hi + n]);
                mma16h(c[1][nt], a[1], s[base_lo + n], s[base_hi + n]);
            }
        }
        if (ch < 7) CP_WAIT0();
        __syncthreads();
    }

#pragma unroll
    for (int mt = 0; mt < 2; mt++) {
        int oc_lo = (my * 8 + warp_m * 2 + mt) * 16 + g;
        int oc_hi = oc_lo + 8;
        float blo = addb ? lb[oc_lo] : 0.f;
        float bhi = addb ? lb[oc_hi] : 0.f;
#pragma unroll
        for (int nt = 0; nt < 8; nt++) {
            int col = n0 + warp_n * 64 + nt * 8 + 2 * tig;
            *(float2*)(out + (size_t)oc_lo * N + col) =
                make_float2(c[mt][nt][0] + blo, c[mt][nt][1] + blo);
            *(float2*)(out + (size_t)oc_hi * N + col) =
                make_float2(c[mt][nt][2] + bhi, c[mt][nt][3] + bhi);
        }
    }
}

// ---------------- reduce split-K partials + bias, all levels --------------
__global__ void reduce_part_all(const float* __restrict__ lb)
{
    int idx = blockIdx.x * 256 + threadIdx.x;
    if (idx >= 1376256) return;
    int lvl, i2, N, S, poff, latoff;
    if (idx < 1048576)      { lvl = 1; i2 = idx;           N = 4096; S = 2; poff = 0;       latoff = 4194304; }
    else if (idx < 1310720) { lvl = 2; i2 = idx - 1048576; N = 1024; S = 4; poff = 2097152; latoff = 5242880; }
    else                    { lvl = 3; i2 = idx - 1310720; N = 256;  S = 8; poff = 3145728; latoff = 5505024; }
    float s = lb[lvl * 256 + i2 / N];
    for (int z = 0; z < S; z++) s += g_part[poff + (size_t)z * 256 * N + i2];
    g_lat[latoff + i2] = s;
}

// ---------------- fused top-down + half2 convert, 4 px / thread -----------
__global__ void upcvt_all()
{
    constexpr int LATOFF[4] = {0, 4194304, 5242880, 5505024};
    int idx4 = blockIdx.x * 256 + threadIdx.x;
    if (idx4 >= 696320) return;
    int lvl, off4, lhw;
    if (idx4 < 524288)      { lvl = 0; off4 = 0;      lhw = 14; }
    else if (idx4 < 655360) { lvl = 1; off4 = 524288; lhw = 12; }
    else if (idx4 < 688128) { lvl = 2; off4 = 655360; lhw = 10; }
    else                    { lvl = 3; off4 = 688128; lhw = 8;  }
    int local = (idx4 - off4) * 4;   // half2 index within level
    int HW = 1 << lhw;
    int c = local >> lhw;
    int i = local & (HW - 1);
    int lw = lhw >> 1;
    int W = 1 << lw;
    int y = i >> lw, x = i & (W - 1);   // x multiple of 4
    float v0[4], v1[4];
    {
        const float* l0 = g_lat + LATOFF[lvl];
        const float4 a = *(const float4*)&l0[(size_t)(2 * c) * HW + i];
        const float4 b = *(const float4*)&l0[(size_t)(2 * c + 1) * HW + i];
        v0[0] = a.x; v0[1] = a.y; v0[2] = a.z; v0[3] = a.w;
        v1[0] = b.x; v1[1] = b.y; v1[2] = b.z; v1[3] = b.w;
    }
#pragma unroll
    for (int j = 1; j < 4; j++) {
        if (lvl + j > 3) break;
        int lj_ = lvl + j;
        int sh = j;
        int Wj = W >> sh;
        int HWj = HW >> (2 * sh);
        const float* lj = g_lat + LATOFF[lj_];
        int ybase = (y >> sh) * Wj;
        if (sh == 1) {
            int e = ybase + (x >> 1);
            float2 a = *(const float2*)&lj[(size_t)(2 * c) * HWj + e];
            float2 b = *(const float2*)&lj[(size_t)(2 * c + 1) * HWj + e];
            v0[0] += a.x; v0[1] += a.x; v0[2] += a.y; v0[3] += a.y;
            v1[0] += b.x; v1[1] += b.x; v1[2] += b.y; v1[3] += b.y;
        } else {
            int e = ybase + (x >> sh);
            float a = lj[(size_t)(2 * c) * HWj + e];
            float b = lj[(size_t)(2 * c + 1) * HWj + e];
#pragma unroll
            for (int t = 0; t < 4; t++) { v0[t] += a; v1[t] += b; }
        }
    }
    uint4 pk;
    pk.x = packh2(v0[0], v1[0]);
    pk.y = packh2(v0[1], v1[1]);
    pk.z = packh2(v0[2], v1[2]);
    pk.w = packh2(v0[3], v1[3]);
    *(uint4*)&g_lath[(size_t)idx4 * 4] = pk;
}

// ---------------- stage 1: per-tap GEMM T_j = W_j * lat (no shift) --------
// grid (170, 9): bx -> (lvl, 128-px block); by = j. oh (oc half) is a param.
__global__ __launch_bounds__(256, 2)
void t_gemm(int oh)
{
    constexpr int HS[4]      = {16384, 4096, 1024, 256};    // HW per level
    constexpr int LATHOFF[4] = {0, 2097152, 2621440, 2752512};
    constexpr int TOFF[4]    = {0, 18874368, 23592960, 24772608};
    constexpr int TSTART[5]  = {0, 128, 160, 168, 170};

    __shared__ uint32_t sB[2][16 * 136];
    const int tid = threadIdx.x;
    const int wid = tid >> 5, lid = tid & 31;
    const int g = lid >> 2, tig = lid & 3;
    const int warp_m = wid & 3, warp_n = wid >> 2;

    int bx = blockIdx.x;
    int lvl = 0;
    if (bx >= TSTART[1]) lvl = (bx >= TSTART[3]) ? 3 : ((bx >= TSTART[2]) ? 2 : 1);
    const int tb = bx - TSTART[lvl];
    const int HW = HS[lvl];
    const int px0 = tb * 128;
    const int j = blockIdx.y;

    const uint32_t* lath = g_lath + LATHOFF[lvl];
    const uint4* wtj = (const uint4*)g_wt + lvl * 73728 + j * 8192;
    const uint32_t sbase = smem_u32(&sB[0][0]);

    float c[2][8][4];
#pragma unroll
    for (int mt = 0; mt < 2; mt++)
#pragma unroll
        for (int nt = 0; nt < 8; nt++)
#pragma unroll
            for (int q = 0; q < 4; q++) c[mt][nt][q] = 0.f;

    auto fill = [&](int ch, int b) {
        const int p0 = ch * 16;
#pragma unroll
        for (int e = tid; e < 512; e += 256) {
            int row = e >> 5, cw = e & 31;
            const uint32_t* src = lath + (size_t)(p0 + row) * HW + px0 + cw * 4;
            uint32_t dst = sbase + (uint32_t)(b * 2176 + row * 136 + cw * 4) * 4u;
            CP_ASYNC16(dst, src);
        }
    };

    fill(0, 0);
    CP_COMMIT();
    CP_WAIT0();
    __syncthreads();

    for (int ch = 0; ch < 8; ch++) {
        const int cur = ch & 1;
        if (ch < 7) {
            fill(ch + 1, cur ^ 1);
            CP_COMMIT();
        }
        const uint32_t* s = &sB[cur][0];
#pragma unroll
        for (int ks = 0; ks < 2; ks++) {
            const int kc = ch * 2 + ks;
            uint32_t a[2][4];
#pragma unroll
            for (int mt = 0; mt < 2; mt++) {
                int t = oh * 8 + warp_m * 2 + mt;
                uint4 av = wtj[(kc * 16 + t) * 32 + lid];
                a[mt][0] = av.x; a[mt][1] = av.y;
                a[mt][2] = av.z; a[mt][3] = av.w;
            }
            const int base_lo = (ks * 8 + tig) * 136;
            const int base_hi = base_lo + 4 * 136;
#pragma unroll
            for (int nt = 0; nt < 8; nt++) {
                int n = warp_n * 64 + nt * 8 + g;
                mma16h(c[0][nt], a[0], s[base_lo + n], s[base_hi + n]);
                mma16h(c[1][nt], a[1], s[base_lo + n], s[base_hi + n]);
            }
        }
        if (ch < 7) CP_WAIT0();
        __syncthreads();
    }

    // ---- epilogue: stage C tile through smem, write coalesced rows ----
    uint32_t* s_c = &sB[0][0];   // 4352 u32 available; need 64*65 = 4160
    const int HW2 = HW >> 1;
    uint32_t* Tb = g_T + TOFF[lvl] + (size_t)(j * 256 + oh * 128) * HW2 + (px0 >> 1);
#pragma unroll
    for (int half = 0; half < 2; half++) {
        __syncthreads();
        if ((warp_m >> 1) == half) {
            const int wm = warp_m & 1;
#pragma unroll
            for (int mt = 0; mt < 2; mt++) {
                int m_lo = wm * 32 + mt * 16 + g;
                int m_hi = m_lo + 8;
#pragma unroll
                for (int nt = 0; nt < 8; nt++) {
                    int cu = warp_n * 32 + nt * 4 + tig;
                    s_c[m_lo * 65 + cu] = packh2(c[mt][nt][0], c[mt][nt][1]);
                    s_c[m_hi * 65 + cu] = packh2(c[mt][nt][2], c[mt][nt][3]);
                }
            }
        }
        __syncthreads();
        const int row = tid >> 2, part = tid & 3;
        uint32_t* dst = Tb + (size_t)(half * 64 + row) * HW2 + part * 16;
        const uint32_t* srcp = &s_c[row * 65 + part * 16];
#pragma unroll
        for (int u = 0; u < 4; u++)
            ((uint4*)dst)[u] = make_uint4(srcp[4 * u], srcp[4 * u + 1],
                                          srcp[4 * u + 2], srcp[4 * u + 3]);
    }
}

// ---------------- stage 2: warp-per-2-rows 9-tap shift-sum (oc half) ------
// grid 1920 x 256. Warp = (lvl, oc-in-half, 2-row strip); oh selects oc half.
__global__ __launch_bounds__(256)
void sum_bn3(int oh,
             const float* __restrict__ bias4,
             const float* __restrict__ bng4, const float* __restrict__ bnb4,
             const float* __restrict__ bnm4, const float* __restrict__ bnv4)
{
    constexpr int INVK[5][9] = {
        {0, 1, 2, 3, 4, 5, 6, 7, 8},
        {1, 2, 5, 0, 4, 8, 3, 6, 7},
        {2, 5, 8, 1, 4, 7, 0, 3, 6},
        {5, 8, 7, 2, 4, 6, 1, 0, 3},
        {8, 7, 6, 5, 4, 3, 2, 1, 0}};
    constexpr int HSW[4]    = {128, 64, 32, 16};
    constexpr int TOFF[4]   = {0, 18874368, 23592960, 24772608};
    constexpr int FEOFFH[4] = {0, 10485760, 13107200, 13762560};
    constexpr int CSTART[5] = {0, 1024, 1536, 1792, 1920};
    constexpr int RBS[4]    = {3, 2, 1, 0};   // log2 row-blocks per oc

    const int wid = threadIdx.x >> 5;
    const int lane = threadIdx.x & 31;

    int bx = blockIdx.x;
    int lvl = 0;
    if (bx >= CSTART[1]) lvl = (bx >= CSTART[3]) ? 3 : ((bx >= CSTART[2]) ? 2 : 1);
    const int local = bx - CSTART[lvl];
    const int rbs = RBS[lvl];
    const int oc = oh * 128 + (local >> rbs);
    const int rblk = local & ((1 << rbs) - 1);
    const int W = HSW[lvl], H = W;
    const int W2 = W >> 1;
    const int HW2 = (W * W) >> 1;
    const int y0 = (rblk * 8 + wid) * 2;
    const int c = 2 * lane;               // u32 column of first output pair
    const bool active = (4 * lane) < W;

    const uint32_t* Tb = g_T + TOFF[lvl] + (size_t)oc * HW2;

    float acc[5][2][4];
#pragma unroll
    for (int r = 0; r < 5; r++)
#pragma unroll
        for (int p = 0; p < 2; p++)
#pragma unroll
            for (int t = 0; t < 4; t++) acc[r][p][t] = 0.f;

#pragma unroll
    for (int j = 0; j < 9; j++) {
        const uint32_t* base = Tb + (size_t)j * 256 * HW2;
        float f[4][8];
#pragma unroll
        for (int d = 0; d < 4; d++) {
            int yr = y0 - 1 + d;
            bool rok = active && ((unsigned)yr < (unsigned)H);
            const uint32_t* rp = base + (size_t)yr * W2;
#pragma unroll
            for (int u = 0; u < 4; u++) {
                int cc = c - 1 + u;
                uint32_t v = (rok && (unsigned)cc < (unsigned)W2) ? rp[cc] : 0u;
                float2 ff = __half22float2(*(const __half2*)&v);
                f[d][2 * u] = ff.x;
                f[d][2 * u + 1] = ff.y;
            }
        }
#pragma unroll
        for (int r = 0; r < 5; r++) {
            const int k = INVK[r][j];
            const int ky = k / 3, kx = k % 3;
#pragma unroll
            for (int t = 0; t < 4; t++) {
                acc[r][0][t] += f[ky][t + kx + 1];
                acc[r][1][t] += f[ky + 1][t + kx + 1];
            }
        }
    }

    // epilogue: bias + BN + relu -> feas (uint2 x 2 rows) + fsum warp-atomic
    const float bv = bias4[lvl * 256 + oc];
    uint32_t* fpb = g_feash + FEOFFH[lvl];
    float fs = 0.f;
#pragma unroll
    for (int r = 0; r < 5; r++) {
        int bi = lvl * 1280 + r * 256 + oc;
        float sc = bng4[bi] * rsqrtf(bnv4[bi] + BN_EPS);
        float sh = bnb4[bi] + (bv - bnm4[bi]) * sc;
        if (active) {
#pragma unroll
            for (int p = 0; p < 2; p++) {
                float v0 = fmaxf(fmaf(acc[r][p][0], sc, sh), 0.f);
                float v1 = fmaxf(fmaf(acc[r][p][1], sc, sh), 0.f);
                float v2 = fmaxf(fmaf(acc[r][p][2], sc, sh), 0.f);
                float v3 = fmaxf(fmaf(acc[r][p][3], sc, sh), 0.f);
                uint2 pk;
                pk.x = packh2(v0, v1);
                pk.y = packh2(v2, v3);
                *(uint2*)&fpb[(size_t)(r * 256 + oc) * HW2 + (size_t)(y0 + p) * W2 + c] = pk;
                fs += v0 + v1 + v2 + v3;
            }
        }
    }
#pragma unroll
    for (int o = 16; o > 0; o >>= 1) fs += __shfl_down_sync(0xffffffffu, fs, o);
    if (lane == 0) atomicAdd(&g_fsum[lvl * 256 + oc], fs);
}

// ---------------- fused fea_z + att: grid(4) x 256 ------------------------
__global__ void fzatt_all(const float* __restrict__ fcw4, const float* __restrict__ fcb4,
                          const float* __restrict__ fcsw4, const float* __restrict__ fcsb4)
{
    constexpr int HWs[4] = {16384, 4096, 1024, 256};
    int lvl = blockIdx.x;
    int tid = threadIdx.x;
    __shared__ float fs[256];
    __shared__ float fz[128];
    fs[tid] = g_fsum[lvl * 256 + tid] * (1.f / (float)HWs[lvl]);
    __syncthreads();
    if (tid < 128) {
        const float* fcw = fcw4 + lvl * 32768 + tid * 256;
        float s = 0.f;
        for (int c = 0; c < 256; c++) s += fcw[c] * fs[c];
        fz[tid] = s + fcb4[lvl * 128 + tid];
    }
    __syncthreads();
    const float* fcsw = fcsw4 + lvl * 163840;
    const float* fcsb = fcsb4 + lvl * 1280;
    float lg[5];
#pragma unroll
    for (int m = 0; m < 5; m++) {
        const float* wrow = fcsw + (m * 256 + tid) * 128;
        float s = 0.f;
        for (int d = 0; d < 128; d++) s += fz[d] * wrow[d];
        lg[m] = s + fcsb[m * 256 + tid];
    }
    float mx = -1e30f;
#pragma unroll
    for (int m = 0; m < 5; m++) mx = fmaxf(mx, lg[m]);
    float den = 0.f;
#pragma unroll
    for (int m = 0; m < 5; m++) { lg[m] = expf(lg[m] - mx); den += lg[m]; }
    float inv = 1.f / den;
#pragma unroll
    for (int m = 0; m < 5; m++) g_att[lvl * 1280 + m * 256 + tid] = lg[m] * inv;
}

// ---------------- out: all levels, flattened (4 px / thread) --------------
__global__ void wsum_all(float* __restrict__ out)
{
    constexpr int FEOFFH[4] = {0, 10485760, 13107200, 13762560};
    constexpr int LATOFF[4] = {0, 4194304, 5242880, 5505024};
    constexpr int HWs[4]    = {16384, 4096, 1024, 256};
    constexpr int BSTART[5] = {0, 4096, 5120, 5376, 5440};
    int b = blockIdx.x;
    int lvl = 0;
    if (b >= BSTART[1]) lvl = (b >= BSTART[3]) ? 3 : ((b >= BSTART[2]) ? 2 : 1);
    int i4 = (b - BSTART[lvl]) * 256 + threadIdx.x;
    int HW = HWs[lvl];
    int hw4 = HW >> 2;
    int c = i4 / hw4;
    int p = i4 - c * hw4;
    const uint32_t* f = g_feash + FEOFFH[lvl];
    const float* att = g_att + lvl * 1280;
    float4 acc = make_float4(0.f, 0.f, 0.f, 0.f);
#pragma unroll
    for (int m = 0; m < 5; m++) {
        float a = att[m * 256 + c];
        uint2 raw = *(const uint2*)&f[(size_t)(m * 256 + c) * (HW >> 1) + p * 2];
        float2 v01 = __half22float2(*(const __half2*)&raw.x);
        float2 v23 = __half22float2(*(const __half2*)&raw.y);
        acc.x = fmaf(a, v01.x, acc.x);
        acc.y = fmaf(a, v01.y, acc.y);
        acc.z = fmaf(a, v23.x, acc.z);
        acc.w = fmaf(a, v23.y, acc.w);
    }
    ((float4*)(out + LATOFF[lvl]))[i4] = acc;
}

// ---------------- launch ----------------
extern "C" void kernel_launch(void* const* d_in, const int* in_sizes, int n_in,
                              void* d_out, int out_size)
{
    // one-time resource creation (first call = uncaptured correctness run)
    static cudaStream_t s2 = nullptr;
    static cudaEvent_t evA = nullptr, evC = nullptr;
    if (s2 == nullptr) {
        cudaStreamCreateWithFlags(&s2, cudaStreamNonBlocking);
        cudaEventCreateWithFlags(&evA, cudaEventDisableTiming);
        cudaEventCreateWithFlags(&evC, cudaEventDisableTiming);
    }

    const float *x[4], *lw[4];
    if (in_sizes[1] == 65536) {           // interleaved: x0,lw0,x1,lw1,...
        for (int i = 0; i < 4; i++) {
            x[i]  = (const float*)d_in[2 * i];
            lw[i] = (const float*)d_in[2 * i + 1];
        }
    } else {                              // grouped: x0..x3, lw0..lw3
        for (int i = 0; i < 4; i++) {
            x[i]  = (const float*)d_in[i];
            lw[i] = (const float*)d_in[4 + i];
        }
    }
    const float* lb   = (const float*)d_in[8];
    const float* aacw = (const float*)d_in[9];
    const float* aacb = (const float*)d_in[10];
    const float* bng  = (const float*)d_in[11];
    const float* bnb  = (const float*)d_in[12];
    const float* bnm  = (const float*)d_in[13];
    const float* bnv  = (const float*)d_in[14];
    const float* fcw  = (const float*)d_in[15];
    const float* fcb  = (const float*)d_in[16];
    const float* fcsw = (const float*)d_in[17];
    const float* fcsb = (const float*)d_in[18];
    float* out = (float*)d_out;

    // 0) fused prep: conv weights (+fsum zero) | lateral weights | x convert
    prep_all<<<10368, 256>>>(aacw, lw[0], lw[1], lw[2], lw[3],
                             x[0], x[1], x[2], x[3]);

    // 1) lateral 1x1 convs, all levels + split-K in one grid
    lat_mma_all<<<dim3(240, 2), 256>>>(lb);
    reduce_part_all<<<5376, 256>>>(lb);

    // 2) fused top-down pathway + half2 convert (4 px / thread)
    upcvt_all<<<2720, 256>>>();

    // 3/4) pipelined: t_gemm(oh0) -> {sum_bn(oh0) || t_gemm(oh1)} -> sum_bn(oh1)
    t_gemm<<<dim3(170, 9), 256>>>(0);
    cudaEventRecord(evA, 0);
    cudaStreamWaitEvent(s2, evA, 0);
    sum_bn3<<<1920, 256, 0, s2>>>(0, aacb, bng, bnb, bnm, bnv);
    cudaEventRecord(evC, s2);
    t_gemm<<<dim3(170, 9), 256>>>(1);
    sum_bn3<<<1920, 256>>>(1, aacb, bng, bnb, bnm, bnv);
    cudaStreamWaitEvent(0, evC, 0);

    // 5) SK fusion tail
    fzatt_all<<<4, 256>>>(fcw, fcb, fcsw, fcsb);
    wsum_all<<<5440, 256>>>(out);

    (void)n_in; (void)out_size;
}

// round 15
// speedup vs baseline: 1.0222x; 1.0222x over previous
#include <cuda_runtime.h>
#include <cuda_fp16.h>
#include <cstdint>
#include <math.h>

// ---------------- scratch (device globals; no allocation) ----------------
__device__ float g_lat[5570560];        // 4 levels of raw laterals (256,H,W)
__device__ uint32_t g_lath[2785280];    // packed half2 combined lat (ic-pair, HW)
__device__ uint32_t g_wt[1179648];      // fp16 conv weights, fragment order
__device__ uint32_t g_lwh[491520];      // fp16 lateral weights, fragment order
__device__ uint32_t g_xh[3932160];      // packed half2 x inputs (k-pair, HW)
__device__ uint32_t g_T[25067520];      // per-tap GEMM outputs T_j, half2 px pairs
__device__ uint32_t g_feash[13926400];  // feas as half2 (px pairs)
__device__ float g_part[3670016];       // split-K partials (all levels)
__device__ float g_fsum[4 * 256];
__device__ float g_att[4 * 5 * 256];

#define BN_EPS 1e-5f

__device__ __forceinline__ uint32_t smem_u32(const void* p) {
    uint32_t a;
    asm("{ .reg .u64 t; cvta.to.shared.u64 t, %1; cvt.u32.u64 %0, t; }" : "=r"(a) : "l"(p));
    return a;
}
#define CP_ASYNC16(dst, src) \
    asm volatile("cp.async.cg.shared.global [%0], [%1], 16;" \
                 :: "r"(dst), "l"(src) : "memory")
#define CP_COMMIT() asm volatile("cp.async.commit_group;" ::: "memory")
#define CP_WAIT0()  asm volatile("cp.async.wait_group 0;" ::: "memory")

__device__ __forceinline__ void mma16h(float* c, const uint32_t* a,
                                       uint32_t b0, uint32_t b1) {
    asm volatile(
        "mma.sync.aligned.m16n8k16.row.col.f32.f16.f16.f32 "
        "{%0,%1,%2,%3}, {%4,%5,%6,%7}, {%8,%9}, {%0,%1,%2,%3};"
        : "+f"(c[0]), "+f"(c[1]), "+f"(c[2]), "+f"(c[3])
        : "r"(a[0]), "r"(a[1]), "r"(a[2]), "r"(a[3]), "r"(b0), "r"(b1));
}
__device__ __forceinline__ uint32_t packh2(float a, float b) {
    uint32_t h0 = __half_as_ushort(__float2half_rn(a));
    uint32_t h1 = __half_as_ushort(__float2half_rn(b));
    return (h1 << 16) | h0;
}

// ---------------- fused prep: conv wt (staged) + lateral wt + x convert ---
// grid: [0,256) wt_transpose staged | [256,736) wt_lat | [736,4576) cvt_x
__global__ void prep_all(const float* __restrict__ aacw,
                         const float* __restrict__ lw0, const float* __restrict__ lw1,
                         const float* __restrict__ lw2, const float* __restrict__ lw3,
                         const float* __restrict__ x0, const float* __restrict__ x1,
                         const float* __restrict__ x2, const float* __restrict__ x3)
{
    __shared__ float sw[9216];   // 16 oc x 64 ic x 9 j (36.8 KB)
    const int bx = blockIdx.x;
    const int tid = threadIdx.x;
    if (bx < 256) {
        // ---- conv weight transpose, smem-staged (coalesced both sides) ----
        if (bx == 0) {
            for (int k = tid; k < 1024; k += 256) g_fsum[k] = 0.f;
        }
        const int lvl = bx >> 6;
        const int rem0 = bx & 63;
        const int t = rem0 >> 2;
        const int icb = rem0 & 3;
        // load 16 oc rows x 576 contiguous floats
        const float* src = aacw + (size_t)(lvl * 256 + t * 16) * 2304 + icb * 576;
#pragma unroll
        for (int e = tid; e < 9216; e += 256) {
            int r = e / 576, o = e - r * 576;
            sw[e] = src[(size_t)r * 2304 + o];
        }
        __syncthreads();
        // emit 4608 packed u32, fully coalesced
        for (int e = tid; e < 4608; e += 256) {
            int j = e / 512;
            int rem = e - j * 512;
            int kk = rem >> 7;
            int li = rem & 127;
            int l = li >> 2, q = li & 3;
            int ocl = (l >> 2) + 8 * (q & 1);
            int icl = kk * 16 + 2 * ((l & 3) + 4 * (q >> 1));
            float w0 = sw[ocl * 576 + icl * 9 + j];
            float w1 = sw[ocl * 576 + (icl + 1) * 9 + j];
            int kc = icb * 4 + kk;
            g_wt[(((lvl * 9 + j) * 16 + kc) * 16 + t) * 128 + li] = packh2(w0, w1);
        }
    } else if (bx < 736) {
        // ---- lateral weight transpose: one uint4 per thread ----
        int idx = (bx - 256) * 256 + tid;    // uint4 index, 122880 total
        int i2 = idx * 4;
        int lvl, off, K;
        if (i2 < 32768)       { lvl = 0; off = 0;      K = 256;  }
        else if (i2 < 98304)  { lvl = 1; off = 32768;  K = 512;  }
        else if (i2 < 229376) { lvl = 2; off = 98304;  K = 1024; }
        else                  { lvl = 3; off = 229376; K = 2048; }
        const float* lw = lvl == 0 ? lw0 : lvl == 1 ? lw1 : lvl == 2 ? lw2 : lw3;
        int loc = i2 - off;
        int l = (loc >> 2) & 31;
        int t = (loc >> 7) & 15;
        int kc = loc >> 11;
        int oc0 = t * 16 + (l >> 2);
        int p0 = kc * 8 + (l & 3);
        float2 a  = *(const float2*)&lw[(size_t)oc0 * K + 2 * p0];
        float2 b  = *(const float2*)&lw[(size_t)(oc0 + 8) * K + 2 * p0];
        float2 cc = *(const float2*)&lw[(size_t)oc0 * K + 2 * (p0 + 4)];
        float2 d  = *(const float2*)&lw[(size_t)(oc0 + 8) * K + 2 * (p0 + 4)];
        uint4 pk;
        pk.x = packh2(a.x, a.y);
        pk.y = packh2(b.x, b.y);
        pk.z = packh2(cc.x, cc.y);
        pk.w = packh2(d.x, d.y);
        ((uint4*)g_lwh)[idx] = pk;
    } else {
        // ---- x -> packed half2, 4 pixels per thread (vectorized) ----
        int idx4 = (bx - 736) * 256 + tid;   // 983040 total
        int lvl, off4, N;
        if (idx4 < 524288)      { lvl = 0; off4 = 0;      N = 16384; }
        else if (idx4 < 786432) { lvl = 1; off4 = 524288; N = 4096;  }
        else if (idx4 < 917504) { lvl = 2; off4 = 786432; N = 1024;  }
        else                    { lvl = 3; off4 = 917504; N = 256;   }
        const float* x = lvl == 0 ? x0 : lvl == 1 ? x1 : lvl == 2 ? x2 : x3;
        int i2 = (idx4 - off4) * 4;
        int p = i2 / N;
        int n = i2 - p * N;                 // multiple of 4
        const float4 a = *(const float4*)&x[(size_t)(2 * p) * N + n];
        const float4 b = *(const float4*)&x[(size_t)(2 * p + 1) * N + n];
        uint4 pk;
        pk.x = packh2(a.x, b.x);
        pk.y = packh2(a.y, b.y);
        pk.z = packh2(a.z, b.z);
        pk.w = packh2(a.w, b.w);
        *(uint4*)&g_xh[(size_t)idx4 * 4] = pk;
    }
}

// ---------------- lateral 1x1 conv, ALL levels + split-K in one grid ------
__global__ __launch_bounds__(256, 2)
void lat_mma_all(const float* __restrict__ lb)
{
    constexpr int SEG[4]   = {0, 128, 192, 224};
    constexpr int NB[4]    = {128, 32, 8, 2};
    constexpr int NS[4]    = {16384, 4096, 1024, 256};
    constexpr int LWOFF[4] = {0, 32768, 98304, 229376};
    constexpr int XOFF[4]  = {0, 2097152, 3145728, 3670016};
    constexpr int POFF[4]  = {0, 0, 2097152, 3145728};

    __shared__ uint32_t sB[2][16 * 136];
    const int tid = threadIdx.x;
    const int wid = tid >> 5, lid = tid & 31;
    const int g = lid >> 2, tig = lid & 3;
    const int warp_m = wid & 3, warp_n = wid >> 2;

    const int bx = blockIdx.x;
    const int lvl = bx >= SEG[3] ? 3 : bx >= SEG[2] ? 2 : bx >= SEG[1] ? 1 : 0;
    const int sub = bx - SEG[lvl];
    const int nb = sub & (NB[lvl] - 1);
    const int z = sub / NB[lvl];
    const int N = NS[lvl];
    const int n0 = nb * 128;
    const int my = blockIdx.y;

    const uint32_t* xh = g_xh + XOFF[lvl];
    const uint4* lw4 = (const uint4*)(g_lwh + LWOFF[lvl]);
    const uint32_t sbase = smem_u32(&sB[0][0]);
    const bool addb = (lvl == 0);
    float* out = addb ? g_lat : (g_part + POFF[lvl] + (size_t)z * 256 * N);

    float c[2][8][4];
#pragma unroll
    for (int mt = 0; mt < 2; mt++)
#pragma unroll
        for (int nt = 0; nt < 8; nt++)
#pragma unroll
            for (int q = 0; q < 4; q++) c[mt][nt][q] = 0.f;

    auto fill = [&](int ch, int b) {
        const int p0 = z * 128 + ch * 16;
#pragma unroll
        for (int e = tid; e < 512; e += 256) {
            int row = e >> 5, cw = e & 31;
            const uint32_t* src = xh + (size_t)(p0 + row) * N + n0 + cw * 4;
            uint32_t dst = sbase + (uint32_t)(b * 2176 + row * 136 + cw * 4) * 4u;
            CP_ASYNC16(dst, src);
        }
    };

    fill(0, 0);
    CP_COMMIT();
    CP_WAIT0();
    __syncthreads();

    for (int ch = 0; ch < 8; ch++) {
        const int cur = ch & 1;
        if (ch < 7) {
            fill(ch + 1, cur ^ 1);
            CP_COMMIT();
        }
        const uint32_t* s = &sB[cur][0];
#pragma unroll
        for (int ks = 0; ks < 2; ks++) {
            const int kc = z * 16 + ch * 2 + ks;
            uint32_t a[2][4];
#pragma unroll
            for (int mt = 0; mt < 2; mt++) {
                int t = my * 8 + warp_m * 2 + mt;
                uint4 av = lw4[(kc * 16 + t) * 32 + lid];
                a[mt][0] = av.x; a[mt][1] = av.y;
                a[mt][2] = av.z; a[mt][3] = av.w;
            }
            const int base_lo = (ks * 8 + tig) * 136;
            const int base_hi = base_lo + 4 * 136;
#pragma unroll
            for (int nt = 0; nt < 8; nt++) {
                int n = warp_n * 64 + nt * 8 + g;
                mma16h(c[0][nt], a[0], s[base_lo + n], s[base_hi + n]);
                mma16h(c[1][nt], a[1], s[base_lo + n], s[base_hi + n]);
            }
        }
        if (ch < 7) CP_WAIT0();
        __syncthreads();
    }

#pragma unroll
    for (int mt = 0; mt < 2; mt++) {
        int oc_lo = (my * 8 + warp_m * 2 + mt) * 16 + g;
        int oc_hi = oc_lo + 8;
        float blo = addb ? lb[oc_lo] : 0.f;
        float bhi = addb ? lb[oc_hi] : 0.f;
#pragma unroll
        for (int nt = 0; nt < 8; nt++) {
            int col = n0 + warp_n * 64 + nt * 8 + 2 * tig;
            *(float2*)(out + (size_t)oc_lo * N + col) =
                make_float2(c[mt][nt][0] + blo, c[mt][nt][1] + blo);
            *(float2*)(out + (size_t)oc_hi * N + col) =
                make_float2(c[mt][nt][2] + bhi, c[mt][nt][3] + bhi);
        }
    }
}

// ---------------- reduce split-K partials + bias, all levels --------------
__global__ void reduce_part_all(const float* __restrict__ lb)
{
    int idx = blockIdx.x * 256 + threadIdx.x;
    if (idx >= 1376256) return;
    int lvl, i2, N, S, poff, latoff;
    if (idx < 1048576)      { lvl = 1; i2 = idx;           N = 4096; S = 2; poff = 0;       latoff = 4194304; }
    else if (idx < 1310720) { lvl = 2; i2 = idx - 1048576; N = 1024; S = 4; poff = 2097152; latoff = 5242880; }
    else                    { lvl = 3; i2 = idx - 1310720; N = 256;  S = 8; poff = 3145728; latoff = 5505024; }
    float s = lb[lvl * 256 + i2 / N];
    for (int z = 0; z < S; z++) s += g_part[poff + (size_t)z * 256 * N + i2];
    g_lat[latoff + i2] = s;
}

// ---------------- fused top-down + half2 convert, 4 px / thread -----------
__global__ void upcvt_all()
{
    constexpr int LATOFF[4] = {0, 4194304, 5242880, 5505024};
    int idx4 = blockIdx.x * 256 + threadIdx.x;
    if (idx4 >= 696320) return;
    int lvl, off4, lhw;
    if (idx4 < 524288)      { lvl = 0; off4 = 0;      lhw = 14; }
    else if (idx4 < 655360) { lvl = 1; off4 = 524288; lhw = 12; }
    else if (idx4 < 688128) { lvl = 2; off4 = 655360; lhw = 10; }
    else                    { lvl = 3; off4 = 688128; lhw = 8;  }
    int local = (idx4 - off4) * 4;   // half2 index within level
    int HW = 1 << lhw;
    int c = local >> lhw;
    int i = local & (HW - 1);
    int lw = lhw >> 1;
    int W = 1 << lw;
    int y = i >> lw, x = i & (W - 1);   // x multiple of 4
    float v0[4], v1[4];
    {
        const float* l0 = g_lat + LATOFF[lvl];
        const float4 a = *(const float4*)&l0[(size_t)(2 * c) * HW + i];
        const float4 b = *(const float4*)&l0[(size_t)(2 * c + 1) * HW + i];
        v0[0] = a.x; v0[1] = a.y; v0[2] = a.z; v0[3] = a.w;
        v1[0] = b.x; v1[1] = b.y; v1[2] = b.z; v1[3] = b.w;
    }
#pragma unroll
    for (int j = 1; j < 4; j++) {
        if (lvl + j > 3) break;
        int lj_ = lvl + j;
        int sh = j;
        int Wj = W >> sh;
        int HWj = HW >> (2 * sh);
        const float* lj = g_lat + LATOFF[lj_];
        int ybase = (y >> sh) * Wj;
        if (sh == 1) {
            int e = ybase + (x >> 1);
            float2 a = *(const float2*)&lj[(size_t)(2 * c) * HWj + e];
            float2 b = *(const float2*)&lj[(size_t)(2 * c + 1) * HWj + e];
            v0[0] += a.x; v0[1] += a.x; v0[2] += a.y; v0[3] += a.y;
            v1[0] += b.x; v1[1] += b.x; v1[2] += b.y; v1[3] += b.y;
        } else {
            int e = ybase + (x >> sh);
            float a = lj[(size_t)(2 * c) * HWj + e];
            float b = lj[(size_t)(2 * c + 1) * HWj + e];
#pragma unroll
            for (int t = 0; t < 4; t++) { v0[t] += a; v1[t] += b; }
        }
    }
    uint4 pk;
    pk.x = packh2(v0[0], v1[0]);
    pk.y = packh2(v0[1], v1[1]);
    pk.z = packh2(v0[2], v1[2]);
    pk.w = packh2(v0[3], v1[3]);
    *(uint4*)&g_lath[(size_t)idx4 * 4] = pk;
}

// ---------------- stage 1: per-tap GEMM T_j = W_j * lat (no shift) --------
// grid (170, 18): bx -> (lvl, 128-px block); by -> (j = by>>1, oc half)
__global__ __launch_bounds__(256, 2)
void t_gemm()
{
    constexpr int HS[4]      = {16384, 4096, 1024, 256};    // HW per level
    constexpr int LATHOFF[4] = {0, 2097152, 2621440, 2752512};
    constexpr int TOFF[4]    = {0, 18874368, 23592960, 24772608};
    constexpr int TSTART[5]  = {0, 128, 160, 168, 170};

    __shared__ uint32_t sB[2][16 * 136];
    const int tid = threadIdx.x;
    const int wid = tid >> 5, lid = tid & 31;
    const int g = lid >> 2, tig = lid & 3;
    const int warp_m = wid & 3, warp_n = wid >> 2;

    int bx = blockIdx.x;
    int lvl = 0;
    if (bx >= TSTART[1]) lvl = (bx >= TSTART[3]) ? 3 : ((bx >= TSTART[2]) ? 2 : 1);
    const int tb = bx - TSTART[lvl];
    const int HW = HS[lvl];
    const int px0 = tb * 128;
    const int j = blockIdx.y >> 1;
    const int oh = blockIdx.y & 1;

    const uint32_t* lath = g_lath + LATHOFF[lvl];
    const uint4* wtj = (const uint4*)g_wt + lvl * 73728 + j * 8192;
    const uint32_t sbase = smem_u32(&sB[0][0]);

    float c[2][8][4];
#pragma unroll
    for (int mt = 0; mt < 2; mt++)
#pragma unroll
        for (int nt = 0; nt < 8; nt++)
#pragma unroll
            for (int q = 0; q < 4; q++) c[mt][nt][q] = 0.f;

    auto fill = [&](int ch, int b) {
        const int p0 = ch * 16;
#pragma unroll
        for (int e = tid; e < 512; e += 256) {
            int row = e >> 5, cw = e & 31;
            const uint32_t* src = lath + (size_t)(p0 + row) * HW + px0 + cw * 4;
            uint32_t dst = sbase + (uint32_t)(b * 2176 + row * 136 + cw * 4) * 4u;
            CP_ASYNC16(dst, src);
        }
    };

    fill(0, 0);
    CP_COMMIT();
    CP_WAIT0();
    __syncthreads();

    for (int ch = 0; ch < 8; ch++) {
        const int cur = ch & 1;
        if (ch < 7) {
            fill(ch + 1, cur ^ 1);
            CP_COMMIT();
        }
        const uint32_t* s = &sB[cur][0];
#pragma unroll
        for (int ks = 0; ks < 2; ks++) {
            const int kc = ch * 2 + ks;
            uint32_t a[2][4];
#pragma unroll
            for (int mt = 0; mt < 2; mt++) {
                int t = oh * 8 + warp_m * 2 + mt;
                uint4 av = wtj[(kc * 16 + t) * 32 + lid];
                a[mt][0] = av.x; a[mt][1] = av.y;
                a[mt][2] = av.z; a[mt][3] = av.w;
            }
            const int base_lo = (ks * 8 + tig) * 136;
            const int base_hi = base_lo + 4 * 136;
#pragma unroll
            for (int nt = 0; nt < 8; nt++) {
                int n = warp_n * 64 + nt * 8 + g;
                mma16h(c[0][nt], a[0], s[base_lo + n], s[base_hi + n]);
                mma16h(c[1][nt], a[1], s[base_lo + n], s[base_hi + n]);
            }
        }
        if (ch < 7) CP_WAIT0();
        __syncthreads();
    }

    // ---- epilogue: stage C tile through smem, write coalesced rows ----
    uint32_t* s_c = &sB[0][0];   // 4352 u32 available; need 64*65 = 4160
    const int HW2 = HW >> 1;
    uint32_t* Tb = g_T + TOFF[lvl] + (size_t)(j * 256 + oh * 128) * HW2 + (px0 >> 1);
#pragma unroll
    for (int half = 0; half < 2; half++) {
        __syncthreads();
        if ((warp_m >> 1) == half) {
            const int wm = warp_m & 1;
#pragma unroll
            for (int mt = 0; mt < 2; mt++) {
                int m_lo = wm * 32 + mt * 16 + g;
                int m_hi = m_lo + 8;
#pragma unroll
                for (int nt = 0; nt < 8; nt++) {
                    int cu = warp_n * 32 + nt * 4 + tig;
                    s_c[m_lo * 65 + cu] = packh2(c[mt][nt][0], c[mt][nt][1]);
                    s_c[m_hi * 65 + cu] = packh2(c[mt][nt][2], c[mt][nt][3]);
                }
            }
        }
        __syncthreads();
        const int row = tid >> 2, part = tid & 3;
        uint32_t* dst = Tb + (size_t)(half * 64 + row) * HW2 + part * 16;
        const uint32_t* srcp = &s_c[row * 65 + part * 16];
#pragma unroll
        for (int u = 0; u < 4; u++)
            ((uint4*)dst)[u] = make_uint4(srcp[4 * u], srcp[4 * u + 1],
                                          srcp[4 * u + 2], srcp[4 * u + 3]);
    }
}

// ---------------- stage 2: warp-per-2-rows 9-tap shift-sum ----------------
__global__ __launch_bounds__(256)
void sum_bn3(const float* __restrict__ bias4,
             const float* __restrict__ bng4, const float* __restrict__ bnb4,
             const float* __restrict__ bnm4, const float* __restrict__ bnv4)
{
    constexpr int INVK[5][9] = {
        {0, 1, 2, 3, 4, 5, 6, 7, 8},
        {1, 2, 5, 0, 4, 8, 3, 6, 7},
        {2, 5, 8, 1, 4, 7, 0, 3, 6},
        {5, 8, 7, 2, 4, 6, 1, 0, 3},
        {8, 7, 6, 5, 4, 3, 2, 1, 0}};
    constexpr int HSW[4]    = {128, 64, 32, 16};
    constexpr int TOFF[4]   = {0, 18874368, 23592960, 24772608};
    constexpr int FEOFFH[4] = {0, 10485760, 13107200, 13762560};
    constexpr int CSTART[5] = {0, 2048, 3072, 3584, 3840};
    constexpr int RBS[4]    = {3, 2, 1, 0};   // log2 row-blocks per oc

    const int wid = threadIdx.x >> 5;
    const int lane = threadIdx.x & 31;

    int bx = blockIdx.x;
    int lvl = 0;
    if (bx >= CSTART[1]) lvl = (bx >= CSTART[3]) ? 3 : ((bx >= CSTART[2]) ? 2 : 1);
    const int local = bx - CSTART[lvl];
    const int rbs = RBS[lvl];
    const int oc = local >> rbs;
    const int rblk = local & ((1 << rbs) - 1);
    const int W = HSW[lvl], H = W;
    const int W2 = W >> 1;
    const int HW2 = (W * W) >> 1;
    const int y0 = (rblk * 8 + wid) * 2;
    const int c = 2 * lane;               // u32 column of first output pair
    const bool active = (4 * lane) < W;

    const uint32_t* Tb = g_T + TOFF[lvl] + (size_t)oc * HW2;

    float acc[5][2][4];
#pragma unroll
    for (int r = 0; r < 5; r++)
#pragma unroll
        for (int p = 0; p < 2; p++)
#pragma unroll
            for (int t = 0; t < 4; t++) acc[r][p][t] = 0.f;

#pragma unroll
    for (int j = 0; j < 9; j++) {
        const uint32_t* base = Tb + (size_t)j * 256 * HW2;
        float f[4][8];
#pragma unroll
        for (int d = 0; d < 4; d++) {
            int yr = y0 - 1 + d;
            bool rok = active && ((unsigned)yr < (unsigned)H);
            const uint32_t* rp = base + (size_t)yr * W2;
#pragma unroll
            for (int u = 0; u < 4; u++) {
                int cc = c - 1 + u;
                uint32_t v = (rok && (unsigned)cc < (unsigned)W2) ? rp[cc] : 0u;
                float2 ff = __half22float2(*(const __half2*)&v);
                f[d][2 * u] = ff.x;
                f[d][2 * u + 1] = ff.y;
            }
        }
#pragma unroll
        for (int r = 0; r < 5; r++) {
            const int k = INVK[r][j];
            const int ky = k / 3, kx = k % 3;
#pragma unroll
            for (int t = 0; t < 4; t++) {
                acc[r][0][t] += f[ky][t + kx + 1];
                acc[r][1][t] += f[ky + 1][t + kx + 1];
            }
        }
    }

    // epilogue: bias + BN + relu -> feas (uint2 x 2 rows) + fsum warp-atomic
    const float bv = bias4[lvl * 256 + oc];
    uint32_t* fpb = g_feash + FEOFFH[lvl];
    float fs = 0.f;
#pragma unroll
    for (int r = 0; r < 5; r++) {
        int bi = lvl * 1280 + r * 256 + oc;
        float sc = bng4[bi] * rsqrtf(bnv4[bi] + BN_EPS);
        float sh = bnb4[bi] + (bv - bnm4[bi]) * sc;
        if (active) {
#pragma unroll
            for (int p = 0; p < 2; p++) {
                float v0 = fmaxf(fmaf(acc[r][p][0], sc, sh), 0.f);
                float v1 = fmaxf(fmaf(acc[r][p][1], sc, sh), 0.f);
                float v2 = fmaxf(fmaf(acc[r][p][2], sc, sh), 0.f);
                float v3 = fmaxf(fmaf(acc[r][p][3], sc, sh), 0.f);
                uint2 pk;
                pk.x = packh2(v0, v1);
                pk.y = packh2(v2, v3);
                *(uint2*)&fpb[(size_t)(r * 256 + oc) * HW2 + (size_t)(y0 + p) * W2 + c] = pk;
                fs += v0 + v1 + v2 + v3;
            }
        }
    }
#pragma unroll
    for (int o = 16; o > 0; o >>= 1) fs += __shfl_down_sync(0xffffffffu, fs, o);
    if (lane == 0) atomicAdd(&g_fsum[lvl * 256 + oc], fs);
}

// ---------------- fused fea_z + att: grid(4) x 256 ------------------------
__global__ void fzatt_all(const float* __restrict__ fcw4, const float* __restrict__ fcb4,
                          const float* __restrict__ fcsw4, const float* __restrict__ fcsb4)
{
    constexpr int HWs[4] = {16384, 4096, 1024, 256};
    int lvl = blockIdx.x;
    int tid = threadIdx.x;
    __shared__ float fs[256];
    __shared__ float fz[128];
    fs[tid] = g_fsum[lvl * 256 + tid] * (1.f / (float)HWs[lvl]);
    __syncthreads();
    if (tid < 128) {
        const float* fcw = fcw4 + lvl * 32768 + tid * 256;
        float s = 0.f;
        for (int c = 0; c < 256; c++) s += fcw[c] * fs[c];
        fz[tid] = s + fcb4[lvl * 128 + tid];
    }
    __syncthreads();
    const float* fcsw = fcsw4 + lvl * 163840;
    const float* fcsb = fcsb4 + lvl * 1280;
    float lg[5];
#pragma unroll
    for (int m = 0; m < 5; m++) {
        const float* wrow = fcsw + (m * 256 + tid) * 128;
        float s = 0.f;
        for (int d = 0; d < 128; d++) s += fz[d] * wrow[d];
        lg[m] = s + fcsb[m * 256 + tid];
    }
    float mx = -1e30f;
#pragma unroll
    for (int m = 0; m < 5; m++) mx = fmaxf(mx, lg[m]);
    float den = 0.f;
#pragma unroll
    for (int m = 0; m < 5; m++) { lg[m] = expf(lg[m] - mx); den += lg[m]; }
    float inv = 1.f / den;
#pragma unroll
    for (int m = 0; m < 5; m++) g_att[lvl * 1280 + m * 256 + tid] = lg[m] * inv;
}

// ---------------- out: all levels, flattened (4 px / thread) --------------
__global__ void wsum_all(float* __restrict__ out)
{
    constexpr int FEOFFH[4] = {0, 10485760, 13107200, 13762560};
    constexpr int LATOFF[4] = {0, 4194304, 5242880, 5505024};
    constexpr int HWs[4]    = {16384, 4096, 1024, 256};
    constexpr int BSTART[5] = {0, 4096, 5120, 5376, 5440};
    int b = blockIdx.x;
    int lvl = 0;
    if (b >= BSTART[1]) lvl = (b >= BSTART[3]) ? 3 : ((b >= BSTART[2]) ? 2 : 1);
    int i4 = (b - BSTART[lvl]) * 256 + threadIdx.x;
    int HW = HWs[lvl];
    int hw4 = HW >> 2;
    int c = i4 / hw4;
    int p = i4 - c * hw4;
    const uint32_t* f = g_feash + FEOFFH[lvl];
    const float* att = g_att + lvl * 1280;
    float4 acc = make_float4(0.f, 0.f, 0.f, 0.f);
#pragma unroll
    for (int m = 0; m < 5; m++) {
        float a = att[m * 256 + c];
        uint2 raw = *(const uint2*)&f[(size_t)(m * 256 + c) * (HW >> 1) + p * 2];
        float2 v01 = __half22float2(*(const __half2*)&raw.x);
        float2 v23 = __half22float2(*(const __half2*)&raw.y);
        acc.x = fmaf(a, v01.x, acc.x);
        acc.y = fmaf(a, v01.y, acc.y);
        acc.z = fmaf(a, v23.x, acc.z);
        acc.w = fmaf(a, v23.y, acc.w);
    }
    ((float4*)(out + LATOFF[lvl]))[i4] = acc;
}

// ---------------- launch ----------------
extern "C" void kernel_launch(void* const* d_in, const int* in_sizes, int n_in,
                              void* d_out, int out_size)
{
    const float *x[4], *lw[4];
    if (in_sizes[1] == 65536) {           // interleaved: x0,lw0,x1,lw1,...
        for (int i = 0; i < 4; i++) {
            x[i]  = (const float*)d_in[2 * i];
            lw[i] = (const float*)d_in[2 * i + 1];
        }
    } else {                              // grouped: x0..x3, lw0..lw3
        for (int i = 0; i < 4; i++) {
            x[i]  = (const float*)d_in[i];
            lw[i] = (const float*)d_in[4 + i];
        }
    }
    const float* lb   = (const float*)d_in[8];
    const float* aacw = (const float*)d_in[9];
    const float* aacb = (const float*)d_in[10];
    const float* bng  = (const float*)d_in[11];
    const float* bnb  = (const float*)d_in[12];
    const float* bnm  = (const float*)d_in[13];
    const float* bnv  = (const float*)d_in[14];
    const float* fcw  = (const float*)d_in[15];
    const float* fcb  = (const float*)d_in[16];
    const float* fcsw = (const float*)d_in[17];
    const float* fcsb = (const float*)d_in[18];
    float* out = (float*)d_out;

    // 0) fused prep: conv weights (staged) | lateral weights | x convert
    prep_all<<<4576, 256>>>(aacw, lw[0], lw[1], lw[2], lw[3],
                            x[0], x[1], x[2], x[3]);

    // 1) lateral 1x1 convs, all levels + split-K in one grid
    lat_mma_all<<<dim3(240, 2), 256>>>(lb);
    reduce_part_all<<<5376, 256>>>(lb);

    // 2) fused top-down pathway + half2 convert (4 px / thread)
    upcvt_all<<<2720, 256>>>();

    // 3) stage 1: nine per-tap GEMMs (coalesced smem-staged epilogue)
    t_gemm<<<dim3(170, 18), 256>>>();

    // 4) stage 2: 2-row-strip 9-tap shift-sum + BN + relu + fused fsum
    sum_bn3<<<3840, 256>>>(aacb, bng, bnb, bnm, bnv);

    // 5) SK fusion tail
    fzatt_all<<<4, 256>>>(fcw, fcb, fcsw, fcsb);
    wsum_all<<<5440, 256>>>(out);

    (void)n_in; (void)out_size;
}

// round 16
// speedup vs baseline: 1.4708x; 1.4390x over previous
#include <cuda_runtime.h>
#include <cuda_fp16.h>
#include <cstdint>
#include <math.h>

// ---------------- scratch (device globals; no allocation) ----------------
__device__ float g_lat[5570560];        // 4 levels of raw laterals (256,H,W)
__device__ uint32_t g_lath[2785280];    // packed half2 combined lat (ic-pair, HW)
__device__ uint32_t g_wt[1179648];      // fp16 conv weights, fragment order
__device__ uint32_t g_lwh[491520];      // fp16 lateral weights, fragment order
__device__ uint32_t g_xh[3932160];      // packed half2 x inputs (k-pair, HW)
__device__ uint32_t g_T[25067520];      // per-tap GEMM outputs T_j, half2 px pairs
__device__ uint32_t g_feash[13926400];  // feas as half2 (px pairs)
__device__ float g_part[3670016];       // split-K partials (all levels)
__device__ float g_fsum[4 * 256];
__device__ float g_fz[4 * 128];
__device__ float g_att[4 * 5 * 256];

#define BN_EPS 1e-5f

__device__ __forceinline__ uint32_t smem_u32(const void* p) {
    uint32_t a;
    asm("{ .reg .u64 t; cvta.to.shared.u64 t, %1; cvt.u32.u64 %0, t; }" : "=r"(a) : "l"(p));
    return a;
}
#define CP_ASYNC16(dst, src) \
    asm volatile("cp.async.cg.shared.global [%0], [%1], 16;" \
                 :: "r"(dst), "l"(src) : "memory")
#define CP_COMMIT() asm volatile("cp.async.commit_group;" ::: "memory")
#define CP_WAIT0()  asm volatile("cp.async.wait_group 0;" ::: "memory")

__device__ __forceinline__ void mma16h(float* c, const uint32_t* a,
                                       uint32_t b0, uint32_t b1) {
    asm volatile(
        "mma.sync.aligned.m16n8k16.row.col.f32.f16.f16.f32 "
        "{%0,%1,%2,%3}, {%4,%5,%6,%7}, {%8,%9}, {%0,%1,%2,%3};"
        : "+f"(c[0]), "+f"(c[1]), "+f"(c[2]), "+f"(c[3])
        : "r"(a[0]), "r"(a[1]), "r"(a[2]), "r"(a[3]), "r"(b0), "r"(b1));
}
__device__ __forceinline__ uint32_t packh2(float a, float b) {
    uint32_t h0 = __half_as_ushort(__float2half_rn(a));
    uint32_t h1 = __half_as_ushort(__float2half_rn(b));
    return (h1 << 16) | h0;
}

// ---------------- fused prep: conv wt (staged) + lateral wt + x convert ---
// grid: [0,256) wt_transpose staged | [256,736) wt_lat | [736,4576) cvt_x
__global__ void prep_all(const float* __restrict__ aacw,
                         const float* __restrict__ lw0, const float* __restrict__ lw1,
                         const float* __restrict__ lw2, const float* __restrict__ lw3,
                         const float* __restrict__ x0, const float* __restrict__ x1,
                         const float* __restrict__ x2, const float* __restrict__ x3)
{
    __shared__ float sw[9216];   // 16 oc x 64 ic x 9 j (36.8 KB)
    const int bx = blockIdx.x;
    const int tid = threadIdx.x;
    if (bx < 256) {
        // ---- conv weight transpose, smem-staged (coalesced both sides) ----
        if (bx == 0) {
            for (int k = tid; k < 1024; k += 256) g_fsum[k] = 0.f;
        }
        const int lvl = bx >> 6;
        const int rem0 = bx & 63;
        const int t = rem0 >> 2;
        const int icb = rem0 & 3;
        const float* src = aacw + (size_t)(lvl * 256 + t * 16) * 2304 + icb * 576;
#pragma unroll
        for (int e = tid; e < 9216; e += 256) {
            int r = e / 576, o = e - r * 576;
            sw[e] = src[(size_t)r * 2304 + o];
        }
        __syncthreads();
        for (int e = tid; e < 4608; e += 256) {
            int j = e / 512;
            int rem = e - j * 512;
            int kk = rem >> 7;
            int li = rem & 127;
            int l = li >> 2, q = li & 3;
            int ocl = (l >> 2) + 8 * (q & 1);
            int icl = kk * 16 + 2 * ((l & 3) + 4 * (q >> 1));
            float w0 = sw[ocl * 576 + icl * 9 + j];
            float w1 = sw[ocl * 576 + (icl + 1) * 9 + j];
            int kc = icb * 4 + kk;
            g_wt[(((lvl * 9 + j) * 16 + kc) * 16 + t) * 128 + li] = packh2(w0, w1);
        }
    } else if (bx < 736) {
        // ---- lateral weight transpose: one uint4 per thread ----
        int idx = (bx - 256) * 256 + tid;    // uint4 index, 122880 total
        int i2 = idx * 4;
        int lvl, off, K;
        if (i2 < 32768)       { lvl = 0; off = 0;      K = 256;  }
        else if (i2 < 98304)  { lvl = 1; off = 32768;  K = 512;  }
        else if (i2 < 229376) { lvl = 2; off = 98304;  K = 1024; }
        else                  { lvl = 3; off = 229376; K = 2048; }
        const float* lw = lvl == 0 ? lw0 : lvl == 1 ? lw1 : lvl == 2 ? lw2 : lw3;
        int loc = i2 - off;
        int l = (loc >> 2) & 31;
        int t = (loc >> 7) & 15;
        int kc = loc >> 11;
        int oc0 = t * 16 + (l >> 2);
        int p0 = kc * 8 + (l & 3);
        float2 a  = *(const float2*)&lw[(size_t)oc0 * K + 2 * p0];
        float2 b  = *(const float2*)&lw[(size_t)(oc0 + 8) * K + 2 * p0];
        float2 cc = *(const float2*)&lw[(size_t)oc0 * K + 2 * (p0 + 4)];
        float2 d  = *(const float2*)&lw[(size_t)(oc0 + 8) * K + 2 * (p0 + 4)];
        uint4 pk;
        pk.x = packh2(a.x, a.y);
        pk.y = packh2(b.x, b.y);
        pk.z = packh2(cc.x, cc.y);
        pk.w = packh2(d.x, d.y);
        ((uint4*)g_lwh)[idx] = pk;
    } else {
        // ---- x -> packed half2, 4 pixels per thread (vectorized) ----
        int idx4 = (bx - 736) * 256 + tid;   // 983040 total
        int lvl, off4, N;
        if (idx4 < 524288)      { lvl = 0; off4 = 0;      N = 16384; }
        else if (idx4 < 786432) { lvl = 1; off4 = 524288; N = 4096;  }
        else if (idx4 < 917504) { lvl = 2; off4 = 786432; N = 1024;  }
        else                    { lvl = 3; off4 = 917504; N = 256;   }
        const float* x = lvl == 0 ? x0 : lvl == 1 ? x1 : lvl == 2 ? x2 : x3;
        int i2 = (idx4 - off4) * 4;
        int p = i2 / N;
        int n = i2 - p * N;                 // multiple of 4
        const float4 a = *(const float4*)&x[(size_t)(2 * p) * N + n];
        const float4 b = *(const float4*)&x[(size_t)(2 * p + 1) * N + n];
        uint4 pk;
        pk.x = packh2(a.x, b.x);
        pk.y = packh2(a.y, b.y);
        pk.z = packh2(a.z, b.z);
        pk.w = packh2(a.w, b.w);
        *(uint4*)&g_xh[(size_t)idx4 * 4] = pk;
    }
}

// ---------------- lateral 1x1 conv, ALL levels + split-K in one grid ------
__global__ __launch_bounds__(256, 2)
void lat_mma_all(const float* __restrict__ lb)
{
    constexpr int SEG[4]   = {0, 128, 192, 224};
    constexpr int NB[4]    = {128, 32, 8, 2};
    constexpr int NS[4]    = {16384, 4096, 1024, 256};
    constexpr int LWOFF[4] = {0, 32768, 98304, 229376};
    constexpr int XOFF[4]  = {0, 2097152, 3145728, 3670016};
    constexpr int POFF[4]  = {0, 0, 2097152, 3145728};

    __shared__ uint32_t sB[2][16 * 136];
    const int tid = threadIdx.x;
    const int wid = tid >> 5, lid = tid & 31;
    const int g = lid >> 2, tig = lid & 3;
    const int warp_m = wid & 3, warp_n = wid >> 2;

    const int bx = blockIdx.x;
    const int lvl = bx >= SEG[3] ? 3 : bx >= SEG[2] ? 2 : bx >= SEG[1] ? 1 : 0;
    const int sub = bx - SEG[lvl];
    const int nb = sub & (NB[lvl] - 1);
    const int z = sub / NB[lvl];
    const int N = NS[lvl];
    const int n0 = nb * 128;
    const int my = blockIdx.y;

    const uint32_t* xh = g_xh + XOFF[lvl];
    const uint4* lw4 = (const uint4*)(g_lwh + LWOFF[lvl]);
    const uint32_t sbase = smem_u32(&sB[0][0]);
    const bool addb = (lvl == 0);
    float* out = addb ? g_lat : (g_part + POFF[lvl] + (size_t)z * 256 * N);

    float c[2][8][4];
#pragma unroll
    for (int mt = 0; mt < 2; mt++)
#pragma unroll
        for (int nt = 0; nt < 8; nt++)
#pragma unroll
            for (int q = 0; q < 4; q++) c[mt][nt][q] = 0.f;

    auto fill = [&](int ch, int b) {
        const int p0 = z * 128 + ch * 16;
#pragma unroll
        for (int e = tid; e < 512; e += 256) {
            int row = e >> 5, cw = e & 31;
            const uint32_t* src = xh + (size_t)(p0 + row) * N + n0 + cw * 4;
            uint32_t dst = sbase + (uint32_t)(b * 2176 + row * 136 + cw * 4) * 4u;
            CP_ASYNC16(dst, src);
        }
    };

    fill(0, 0);
    CP_COMMIT();
    CP_WAIT0();
    __syncthreads();

    for (int ch = 0; ch < 8; ch++) {
        const int cur = ch & 1;
        if (ch < 7) {
            fill(ch + 1, cur ^ 1);
            CP_COMMIT();
        }
        const uint32_t* s = &sB[cur][0];
#pragma unroll
        for (int ks = 0; ks < 2; ks++) {
            const int kc = z * 16 + ch * 2 + ks;
            uint32_t a[2][4];
#pragma unroll
            for (int mt = 0; mt < 2; mt++) {
                int t = my * 8 + warp_m * 2 + mt;
                uint4 av = lw4[(kc * 16 + t) * 32 + lid];
                a[mt][0] = av.x; a[mt][1] = av.y;
                a[mt][2] = av.z; a[mt][3] = av.w;
            }
            const int base_lo = (ks * 8 + tig) * 136;
            const int base_hi = base_lo + 4 * 136;
#pragma unroll
            for (int nt = 0; nt < 8; nt++) {
                int n = warp_n * 64 + nt * 8 + g;
                mma16h(c[0][nt], a[0], s[base_lo + n], s[base_hi + n]);
                mma16h(c[1][nt], a[1], s[base_lo + n], s[base_hi + n]);
            }
        }
        if (ch < 7) CP_WAIT0();
        __syncthreads();
    }

#pragma unroll
    for (int mt = 0; mt < 2; mt++) {
        int oc_lo = (my * 8 + warp_m * 2 + mt) * 16 + g;
        int oc_hi = oc_lo + 8;
        float blo = addb ? lb[oc_lo] : 0.f;
        float bhi = addb ? lb[oc_hi] : 0.f;
#pragma unroll
        for (int nt = 0; nt < 8; nt++) {
            int col = n0 + warp_n * 64 + nt * 8 + 2 * tig;
            *(float2*)(out + (size_t)oc_lo * N + col) =
                make_float2(c[mt][nt][0] + blo, c[mt][nt][1] + blo);
            *(float2*)(out + (size_t)oc_hi * N + col) =
                make_float2(c[mt][nt][2] + bhi, c[mt][nt][3] + bhi);
        }
    }
}

// ---------------- reduce split-K partials + bias, all levels --------------
__global__ void reduce_part_all(const float* __restrict__ lb)
{
    int idx = blockIdx.x * 256 + threadIdx.x;
    if (idx >= 1376256) return;
    int lvl, i2, N, S, poff, latoff;
    if (idx < 1048576)      { lvl = 1; i2 = idx;           N = 4096; S = 2; poff = 0;       latoff = 4194304; }
    else if (idx < 1310720) { lvl = 2; i2 = idx - 1048576; N = 1024; S = 4; poff = 2097152; latoff = 5242880; }
    else                    { lvl = 3; i2 = idx - 1310720; N = 256;  S = 8; poff = 3145728; latoff = 5505024; }
    float s = lb[lvl * 256 + i2 / N];
    for (int z = 0; z < S; z++) s += g_part[poff + (size_t)z * 256 * N + i2];
    g_lat[latoff + i2] = s;
}

// ---------------- fused top-down + half2 convert, 4 px / thread -----------
__global__ void upcvt_all()
{
    constexpr int LATOFF[4] = {0, 4194304, 5242880, 5505024};
    int idx4 = blockIdx.x * 256 + threadIdx.x;
    if (idx4 >= 696320) return;
    int lvl, off4, lhw;
    if (idx4 < 524288)      { lvl = 0; off4 = 0;      lhw = 14; }
    else if (idx4 < 655360) { lvl = 1; off4 = 524288; lhw = 12; }
    else if (idx4 < 688128) { lvl = 2; off4 = 655360; lhw = 10; }
    else                    { lvl = 3; off4 = 688128; lhw = 8;  }
    int local = (idx4 - off4) * 4;   // half2 index within level
    int HW = 1 << lhw;
    int c = local >> lhw;
    int i = local & (HW - 1);
    int lw = lhw >> 1;
    int W = 1 << lw;
    int y = i >> lw, x = i & (W - 1);   // x multiple of 4
    float v0[4], v1[4];
    {
        const float* l0 = g_lat + LATOFF[lvl];
        const float4 a = *(const float4*)&l0[(size_t)(2 * c) * HW + i];
        const float4 b = *(const float4*)&l0[(size_t)(2 * c + 1) * HW + i];
        v0[0] = a.x; v0[1] = a.y; v0[2] = a.z; v0[3] = a.w;
        v1[0] = b.x; v1[1] = b.y; v1[2] = b.z; v1[3] = b.w;
    }
#pragma unroll
    for (int j = 1; j < 4; j++) {
        if (lvl + j > 3) break;
        int lj_ = lvl + j;
        int sh = j;
        int Wj = W >> sh;
        int HWj = HW >> (2 * sh);
        const float* lj = g_lat + LATOFF[lj_];
        int ybase = (y >> sh) * Wj;
        if (sh == 1) {
            int e = ybase + (x >> 1);
            float2 a = *(const float2*)&lj[(size_t)(2 * c) * HWj + e];
            float2 b = *(const float2*)&lj[(size_t)(2 * c + 1) * HWj + e];
            v0[0] += a.x; v0[1] += a.x; v0[2] += a.y; v0[3] += a.y;
            v1[0] += b.x; v1[1] += b.x; v1[2] += b.y; v1[3] += b.y;
        } else {
            int e = ybase + (x >> sh);
            float a = lj[(size_t)(2 * c) * HWj + e];
            float b = lj[(size_t)(2 * c + 1) * HWj + e];
#pragma unroll
            for (int t = 0; t < 4; t++) { v0[t] += a; v1[t] += b; }
        }
    }
    uint4 pk;
    pk.x = packh2(v0[0], v1[0]);
    pk.y = packh2(v0[1], v1[1]);
    pk.z = packh2(v0[2], v1[2]);
    pk.w = packh2(v0[3], v1[3]);
    *(uint4*)&g_lath[(size_t)idx4 * 4] = pk;
}

// ---------------- stage 1: per-tap GEMM T_j = W_j * lat (no shift) --------
// grid (170, 18): bx -> (lvl, 128-px block); by -> (j = by>>1, oc half)
__global__ __launch_bounds__(256, 2)
void t_gemm()
{
    constexpr int HS[4]      = {16384, 4096, 1024, 256};    // HW per level
    constexpr int LATHOFF[4] = {0, 2097152, 2621440, 2752512};
    constexpr int TOFF[4]    = {0, 18874368, 23592960, 24772608};
    constexpr int TSTART[5]  = {0, 128, 160, 168, 170};

    __shared__ uint32_t sB[2][16 * 136];
    const int tid = threadIdx.x;
    const int wid = tid >> 5, lid = tid & 31;
    const int g = lid >> 2, tig = lid & 3;
    const int warp_m = wid & 3, warp_n = wid >> 2;

    int bx = blockIdx.x;
    int lvl = 0;
    if (bx >= TSTART[1]) lvl = (bx >= TSTART[3]) ? 3 : ((bx >= TSTART[2]) ? 2 : 1);
    const int tb = bx - TSTART[lvl];
    const int HW = HS[lvl];
    const int px0 = tb * 128;
    const int j = blockIdx.y >> 1;
    const int oh = blockIdx.y & 1;

    const uint32_t* lath = g_lath + LATHOFF[lvl];
    const uint4* wtj = (const uint4*)g_wt + lvl * 73728 + j * 8192;
    const uint32_t sbase = smem_u32(&sB[0][0]);

    float c[2][8][4];
#pragma unroll
    for (int mt = 0; mt < 2; mt++)
#pragma unroll
        for (int nt = 0; nt < 8; nt++)
#pragma unroll
            for (int q = 0; q < 4; q++) c[mt][nt][q] = 0.f;

    auto fill = [&](int ch, int b) {
        const int p0 = ch * 16;
#pragma unroll
        for (int e = tid; e < 512; e += 256) {
            int row = e >> 5, cw = e & 31;
            const uint32_t* src = lath + (size_t)(p0 + row) * HW + px0 + cw * 4;
            uint32_t dst = sbase + (uint32_t)(b * 2176 + row * 136 + cw * 4) * 4u;
            CP_ASYNC16(dst, src);
        }
    };

    fill(0, 0);
    CP_COMMIT();
    CP_WAIT0();
    __syncthreads();

    for (int ch = 0; ch < 8; ch++) {
        const int cur = ch & 1;
        if (ch < 7) {
            fill(ch + 1, cur ^ 1);
            CP_COMMIT();
        }
        const uint32_t* s = &sB[cur][0];
#pragma unroll
        for (int ks = 0; ks < 2; ks++) {
            const int kc = ch * 2 + ks;
            uint32_t a[2][4];
#pragma unroll
            for (int mt = 0; mt < 2; mt++) {
                int t = oh * 8 + warp_m * 2 + mt;
                uint4 av = wtj[(kc * 16 + t) * 32 + lid];
                a[mt][0] = av.x; a[mt][1] = av.y;
                a[mt][2] = av.z; a[mt][3] = av.w;
            }
            const int base_lo = (ks * 8 + tig) * 136;
            const int base_hi = base_lo + 4 * 136;
#pragma unroll
            for (int nt = 0; nt < 8; nt++) {
                int n = warp_n * 64 + nt * 8 + g;
                mma16h(c[0][nt], a[0], s[base_lo + n], s[base_hi + n]);
                mma16h(c[1][nt], a[1], s[base_lo + n], s[base_hi + n]);
            }
        }
        if (ch < 7) CP_WAIT0();
        __syncthreads();
    }

    // ---- epilogue: stage C tile through smem, write coalesced rows ----
    uint32_t* s_c = &sB[0][0];   // 4352 u32 available; need 64*65 = 4160
    const int HW2 = HW >> 1;
    uint32_t* Tb = g_T + TOFF[lvl] + (size_t)(j * 256 + oh * 128) * HW2 + (px0 >> 1);
#pragma unroll
    for (int half = 0; half < 2; half++) {
        __syncthreads();
        if ((warp_m >> 1) == half) {
            const int wm = warp_m & 1;
#pragma unroll
            for (int mt = 0; mt < 2; mt++) {
                int m_lo = wm * 32 + mt * 16 + g;
                int m_hi = m_lo + 8;
#pragma unroll
                for (int nt = 0; nt < 8; nt++) {
                    int cu = warp_n * 32 + nt * 4 + tig;
                    s_c[m_lo * 65 + cu] = packh2(c[mt][nt][0], c[mt][nt][1]);
                    s_c[m_hi * 65 + cu] = packh2(c[mt][nt][2], c[mt][nt][3]);
                }
            }
        }
        __syncthreads();
        const int row = tid >> 2, part = tid & 3;
        uint32_t* dst = Tb + (size_t)(half * 64 + row) * HW2 + part * 16;
        const uint32_t* srcp = &s_c[row * 65 + part * 16];
#pragma unroll
        for (int u = 0; u < 4; u++)
            ((uint4*)dst)[u] = make_uint4(srcp[4 * u], srcp[4 * u + 1],
                                          srcp[4 * u + 2], srcp[4 * u + 3]);
    }
}

// ---------------- stage 2 v4: aligned uint2 loads + shfl halo -------------
// grid 3840 x 256. Warp = (lvl, oc, 2-row strip); lane = 4 px per row.
__global__ __launch_bounds__(256)
void sum_bn4(const float* __restrict__ bias4,
             const float* __restrict__ bng4, const float* __restrict__ bnb4,
             const float* __restrict__ bnm4, const float* __restrict__ bnv4)
{
    constexpr int INVK[5][9] = {
        {0, 1, 2, 3, 4, 5, 6, 7, 8},
        {1, 2, 5, 0, 4, 8, 3, 6, 7},
        {2, 5, 8, 1, 4, 7, 0, 3, 6},
        {5, 8, 7, 2, 4, 6, 1, 0, 3},
        {8, 7, 6, 5, 4, 3, 2, 1, 0}};
    constexpr int HSW[4]    = {128, 64, 32, 16};
    constexpr int TOFF[4]   = {0, 18874368, 23592960, 24772608};
    constexpr int FEOFFH[4] = {0, 10485760, 13107200, 13762560};
    constexpr int CSTART[5] = {0, 2048, 3072, 3584, 3840};
    constexpr int RBS[4]    = {3, 2, 1, 0};   // log2 row-blocks per oc

    const int wid = threadIdx.x >> 5;
    const int lane = threadIdx.x & 31;

    int bx = blockIdx.x;
    int lvl = 0;
    if (bx >= CSTART[1]) lvl = (bx >= CSTART[3]) ? 3 : ((bx >= CSTART[2]) ? 2 : 1);
    const int local = bx - CSTART[lvl];
    const int rbs = RBS[lvl];
    const int oc = local >> rbs;
    const int rblk = local & ((1 << rbs) - 1);
    const int W = HSW[lvl], H = W;
    const int W2 = W >> 1;
    const int HW2 = (W * W) >> 1;
    const int y0 = (rblk * 8 + wid) * 2;
    const int c = 2 * lane;               // u32 column of first output pair
    const int x0 = 4 * lane;              // first output pixel (float)
    const bool active = x0 < W;
    const bool has_right = (x0 + 4) < W;  // right halo from lane+1 valid

    const uint32_t* Tb = g_T + TOFF[lvl] + (size_t)oc * HW2;

    float acc[5][2][4];
#pragma unroll
    for (int r = 0; r < 5; r++)
#pragma unroll
        for (int p = 0; p < 2; p++)
#pragma unroll
            for (int t = 0; t < 4; t++) acc[r][p][t] = 0.f;

#pragma unroll
    for (int j = 0; j < 9; j++) {
        const uint32_t* base = Tb + (size_t)j * 256 * HW2;
        // window f[d][0..5] = T at floats x0-1 .. x0+4 (rows y0-1..y0+2)
        float f[4][6];
#pragma unroll
        for (int d = 0; d < 4; d++) {
            int yr = y0 - 1 + d;
            bool rok = active && ((unsigned)yr < (unsigned)H);
            uint2 v = make_uint2(0u, 0u);
            if (rok) v = *(const uint2*)&base[(size_t)yr * W2 + c];
            float2 a = __half22float2(*(const __half2*)&v.x);
            float2 b = __half22float2(*(const __half2*)&v.y);
            f[d][1] = a.x; f[d][2] = a.y; f[d][3] = b.x; f[d][4] = b.y;
            float lf = __shfl_up_sync(0xffffffffu, b.y, 1);
            float rt = __shfl_down_sync(0xffffffffu, a.x, 1);
            f[d][0] = (lane == 0) ? 0.f : lf;
            f[d][5] = has_right ? rt : 0.f;
        }
#pragma unroll
        for (int r = 0; r < 5; r++) {
            const int k = INVK[r][j];
            const int ky = k / 3, kx = k % 3;
#pragma unroll
            for (int t = 0; t < 4; t++) {
                acc[r][0][t] += f[ky][t + kx];
                acc[r][1][t] += f[ky + 1][t + kx];
            }
        }
    }

    // epilogue: bias + BN + relu -> feas (uint2 x 2 rows) + fsum warp-atomic
    const float bv = bias4[lvl * 256 + oc];
    uint32_t* fpb = g_feash + FEOFFH[lvl];
    float fs = 0.f;
#pragma unroll
    for (int r = 0; r < 5; r++) {
        int bi = lvl * 1280 + r * 256 + oc;
        float sc = bng4[bi] * rsqrtf(bnv4[bi] + BN_EPS);
        float sh = bnb4[bi] + (bv - bnm4[bi]) * sc;
        if (active) {
#pragma unroll
            for (int p = 0; p < 2; p++) {
                float v0 = fmaxf(fmaf(acc[r][p][0], sc, sh), 0.f);
                float v1 = fmaxf(fmaf(acc[r][p][1], sc, sh), 0.f);
                float v2 = fmaxf(fmaf(acc[r][p][2], sc, sh), 0.f);
                float v3 = fmaxf(fmaf(acc[r][p][3], sc, sh), 0.f);
                uint2 pk;
                pk.x = packh2(v0, v1);
                pk.y = packh2(v2, v3);
                *(uint2*)&fpb[(size_t)(r * 256 + oc) * HW2 + (size_t)(y0 + p) * W2 + c] = pk;
                fs += v0 + v1 + v2 + v3;
            }
        }
    }
#pragma unroll
    for (int o = 16; o > 0; o >>= 1) fs += __shfl_down_sync(0xffffffffu, fs, o);
    if (lane == 0) atomicAdd(&g_fsum[lvl * 256 + oc], fs);
}

// ---------------- fea_z: grid (8, 4), warp-reduced (coalesced) ------------
__global__ void fz_all(const float* __restrict__ fcw4, const float* __restrict__ fcb4)
{
    constexpr int HWs[4] = {16384, 4096, 1024, 256};
    int lvl = blockIdx.y;
    const float* fcw = fcw4 + lvl * 32768;
    const float* fcb = fcb4 + lvl * 128;
    float inv = 1.f / (float)HWs[lvl];
    int g = threadIdx.x >> 4;
    int lane = threadIdx.x & 15;
    int d = blockIdx.x * 16 + g;
    float s = 0.f;
    for (int c = lane; c < 256; c += 16)
        s += fcw[d * 256 + c] * (g_fsum[lvl * 256 + c] * inv);
#pragma unroll
    for (int o = 8; o > 0; o >>= 1) s += __shfl_down_sync(0xffffffffu, s, o, 16);
    if (lane == 0) g_fz[lvl * 128 + d] = s + fcb[d];
}

// ---------------- att: grid (32, 4), lanes over d (coalesced) -------------
__global__ void att_all(const float* __restrict__ fcsw4, const float* __restrict__ fcsb4)
{
    int lvl = blockIdx.y;
    const float* fcsw = fcsw4 + lvl * 163840;
    const float* fcsb = fcsb4 + lvl * 1280;
    __shared__ float fz[128];
    if (threadIdx.x < 128) fz[threadIdx.x] = g_fz[lvl * 128 + threadIdx.x];
    __syncthreads();
    int cl = threadIdx.x >> 5;
    int lane = threadIdx.x & 31;
    int c = blockIdx.x * 8 + cl;
    float lg[5];
#pragma unroll
    for (int m = 0; m < 5; m++) {
        float s = 0.f;
#pragma unroll
        for (int i = 0; i < 4; i++) {
            int d = lane + i * 32;
            s += fz[d] * fcsw[((m * 256 + c) * 128) + d];
        }
#pragma unroll
        for (int o = 16; o > 0; o >>= 1) s += __shfl_down_sync(0xffffffffu, s, o);
        lg[m] = s;
    }
    if (lane == 0) {
        float mx = -1e30f;
#pragma unroll
        for (int m = 0; m < 5; m++) {
            lg[m] += fcsb[m * 256 + c];
            mx = fmaxf(mx, lg[m]);
        }
        float den = 0.f;
#pragma unroll
        for (int m = 0; m < 5; m++) { lg[m] = expf(lg[m] - mx); den += lg[m]; }
        float inv = 1.f / den;
#pragma unroll
        for (int m = 0; m < 5; m++) g_att[lvl * 1280 + m * 256 + c] = lg[m] * inv;
    }
}

// ---------------- out: all levels, 8 px / thread --------------------------
__global__ void wsum_all(float* __restrict__ out)
{
    constexpr int FEOFFH[4] = {0, 10485760, 13107200, 13762560};
    constexpr int LATOFF[4] = {0, 4194304, 5242880, 5505024};
    constexpr int HWs[4]    = {16384, 4096, 1024, 256};
    constexpr int BSTART[5] = {0, 2048, 2560, 2688, 2720};
    int b = blockIdx.x;
    int lvl = 0;
    if (b >= BSTART[1]) lvl = (b >= BSTART[3]) ? 3 : ((b >= BSTART[2]) ? 2 : 1);
    int i8 = (b - BSTART[lvl]) * 256 + threadIdx.x;
    int HW = HWs[lvl];
    int hw8 = HW >> 3;
    int c = i8 / hw8;
    int p = i8 - c * hw8;
    const uint32_t* f = g_feash + FEOFFH[lvl];
    const float* att = g_att + lvl * 1280;
    float acc[8];
#pragma unroll
    for (int t = 0; t < 8; t++) acc[t] = 0.f;
#pragma unroll
    for (int m = 0; m < 5; m++) {
        float a = att[m * 256 + c];
        uint4 raw = *(const uint4*)&f[(size_t)(m * 256 + c) * (HW >> 1) + p * 4];
        float2 v0 = __half22float2(*(const __half2*)&raw.x);
        float2 v1 = __half22float2(*(const __half2*)&raw.y);
        float2 v2 = __half22float2(*(const __half2*)&raw.z);
        float2 v3 = __half22float2(*(const __half2*)&raw.w);
        acc[0] = fmaf(a, v0.x, acc[0]); acc[1] = fmaf(a, v0.y, acc[1]);
        acc[2] = fmaf(a, v1.x, acc[2]); acc[3] = fmaf(a, v1.y, acc[3]);
        acc[4] = fmaf(a, v2.x, acc[4]); acc[5] = fmaf(a, v2.y, acc[5]);
        acc[6] = fmaf(a, v3.x, acc[6]); acc[7] = fmaf(a, v3.y, acc[7]);
    }
    float* op = out + LATOFF[lvl] + (size_t)i8 * 8;
    *(float4*)op = make_float4(acc[0], acc[1], acc[2], acc[3]);
    *(float4*)(op + 4) = make_float4(acc[4], acc[5], acc[6], acc[7]);
}

// ---------------- launch ----------------
extern "C" void kernel_launch(void* const* d_in, const int* in_sizes, int n_in,
                              void* d_out, int out_size)
{
    const float *x[4], *lw[4];
    if (in_sizes[1] == 65536) {           // interleaved: x0,lw0,x1,lw1,...
        for (int i = 0; i < 4; i++) {
            x[i]  = (const float*)d_in[2 * i];
            lw[i] = (const float*)d_in[2 * i + 1];
        }
    } else {                              // grouped: x0..x3, lw0..lw3
        for (int i = 0; i < 4; i++) {
            x[i]  = (const float*)d_in[i];
            lw[i] = (const float*)d_in[4 + i];
        }
    }
    const float* lb   = (const float*)d_in[8];
    const float* aacw = (const float*)d_in[9];
    const float* aacb = (const float*)d_in[10];
    const float* bng  = (const float*)d_in[11];
    const float* bnb  = (const float*)d_in[12];
    const float* bnm  = (const float*)d_in[13];
    const float* bnv  = (const float*)d_in[14];
    const float* fcw  = (const float*)d_in[15];
    const float* fcb  = (const float*)d_in[16];
    const float* fcsw = (const float*)d_in[17];
    const float* fcsb = (const float*)d_in[18];
    float* out = (float*)d_out;

    // 0) fused prep: conv weights (staged) | lateral weights | x convert
    prep_all<<<4576, 256>>>(aacw, lw[0], lw[1], lw[2], lw[3],
                            x[0], x[1], x[2], x[3]);

    // 1) lateral 1x1 convs, all levels + split-K in one grid
    lat_mma_all<<<dim3(240, 2), 256>>>(lb);
    reduce_part_all<<<5376, 256>>>(lb);

    // 2) fused top-down pathway + half2 convert (4 px / thread)
    upcvt_all<<<2720, 256>>>();

    // 3) stage 1: nine per-tap GEMMs (coalesced smem-staged epilogue)
    t_gemm<<<dim3(170, 18), 256>>>();

    // 4) stage 2 v4: shfl-halo 9-tap shift-sum + BN + relu + fused fsum
    sum_bn4<<<3840, 256>>>(aacb, bng, bnb, bnm, bnv);

    // 5) SK fusion tail (coalesced split kernels)
    fz_all<<<dim3(8, 4), 256>>>(fcw, fcb);
    att_all<<<dim3(32, 4), 256>>>(fcsw, fcsb);
    wsum_all<<<2720, 256>>>(out);

    (void)n_in; (void)out_size;
}

// round 17
// speedup vs baseline: 1.4923x; 1.0146x over previous
#include <cuda_runtime.h>
#include <cuda_fp16.h>
#include <cstdint>
#include <math.h>

// ---------------- scratch (device globals; no allocation) ----------------
__device__ float g_lat[5570560];        // 4 levels of combined laterals
__device__ uint32_t g_lath[2785280];    // packed half2 combined lat (ic-pair, HW)
__device__ uint32_t g_wt[1179648];      // fp16 conv weights, fragment order
__device__ uint32_t g_lwh[491520];      // fp16 lateral weights, fragment order
__device__ uint32_t g_xh[3932160];      // packed half2 x inputs (k-pair, HW)
__device__ uint32_t g_T[25067520];      // per-tap GEMM outputs T_j, half2 px pairs
__device__ uint32_t g_feash[13926400];  // feas as half2 (px pairs)
__device__ float g_fsum[4 * 256];
__device__ float g_fz[4 * 128];
__device__ float g_att[4 * 5 * 256];

#define BN_EPS 1e-5f

__device__ __forceinline__ uint32_t smem_u32(const void* p) {
    uint32_t a;
    asm("{ .reg .u64 t; cvta.to.shared.u64 t, %1; cvt.u32.u64 %0, t; }" : "=r"(a) : "l"(p));
    return a;
}
#define CP_ASYNC16(dst, src) \
    asm volatile("cp.async.cg.shared.global [%0], [%1], 16;" \
                 :: "r"(dst), "l"(src) : "memory")
#define CP_COMMIT() asm volatile("cp.async.commit_group;" ::: "memory")
#define CP_WAIT0()  asm volatile("cp.async.wait_group 0;" ::: "memory")

__device__ __forceinline__ void mma16h(float* c, const uint32_t* a,
                                       uint32_t b0, uint32_t b1) {
    asm volatile(
        "mma.sync.aligned.m16n8k16.row.col.f32.f16.f16.f32 "
        "{%0,%1,%2,%3}, {%4,%5,%6,%7}, {%8,%9}, {%0,%1,%2,%3};"
        : "+f"(c[0]), "+f"(c[1]), "+f"(c[2]), "+f"(c[3])
        : "r"(a[0]), "r"(a[1]), "r"(a[2]), "r"(a[3]), "r"(b0), "r"(b1));
}
__device__ __forceinline__ uint32_t packh2(float a, float b) {
    uint32_t h0 = __half_as_ushort(__float2half_rn(a));
    uint32_t h1 = __half_as_ushort(__float2half_rn(b));
    return (h1 << 16) | h0;
}

// ---------------- fused prep: conv wt + lat wt + x convert + lat-bias init
// grid: [0,256) wt_transpose | [256,736) wt_lat | [736,4576) cvt_x
//       [4576,5920) init g_lat lvl1-3 with bias
__global__ void prep_all(const float* __restrict__ aacw,
                         const float* __restrict__ lw0, const float* __restrict__ lw1,
                         const float* __restrict__ lw2, const float* __restrict__ lw3,
                         const float* __restrict__ x0, const float* __restrict__ x1,
                         const float* __restrict__ x2, const float* __restrict__ x3,
                         const float* __restrict__ lb)
{
    __shared__ float sw[9216];   // 16 oc x 64 ic x 9 j (36.8 KB)
    const int bx = blockIdx.x;
    const int tid = threadIdx.x;
    if (bx < 256) {
        // ---- conv weight transpose, smem-staged (coalesced both sides) ----
        if (bx == 0) {
            for (int k = tid; k < 1024; k += 256) g_fsum[k] = 0.f;
        }
        const int lvl = bx >> 6;
        const int rem0 = bx & 63;
        const int t = rem0 >> 2;
        const int icb = rem0 & 3;
        const float* src = aacw + (size_t)(lvl * 256 + t * 16) * 2304 + icb * 576;
#pragma unroll
        for (int e = tid; e < 9216; e += 256) {
            int r = e / 576, o = e - r * 576;
            sw[e] = src[(size_t)r * 2304 + o];
        }
        __syncthreads();
        for (int e = tid; e < 4608; e += 256) {
            int j = e / 512;
            int rem = e - j * 512;
            int kk = rem >> 7;
            int li = rem & 127;
            int l = li >> 2, q = li & 3;
            int ocl = (l >> 2) + 8 * (q & 1);
            int icl = kk * 16 + 2 * ((l & 3) + 4 * (q >> 1));
            float w0 = sw[ocl * 576 + icl * 9 + j];
            float w1 = sw[ocl * 576 + (icl + 1) * 9 + j];
            int kc = icb * 4 + kk;
            g_wt[(((lvl * 9 + j) * 16 + kc) * 16 + t) * 128 + li] = packh2(w0, w1);
        }
    } else if (bx < 736) {
        // ---- lateral weight transpose: one uint4 per thread ----
        int idx = (bx - 256) * 256 + tid;    // uint4 index, 122880 total
        int i2 = idx * 4;
        int lvl, off, K;
        if (i2 < 32768)       { lvl = 0; off = 0;      K = 256;  }
        else if (i2 < 98304)  { lvl = 1; off = 32768;  K = 512;  }
        else if (i2 < 229376) { lvl = 2; off = 98304;  K = 1024; }
        else                  { lvl = 3; off = 229376; K = 2048; }
        const float* lw = lvl == 0 ? lw0 : lvl == 1 ? lw1 : lvl == 2 ? lw2 : lw3;
        int loc = i2 - off;
        int l = (loc >> 2) & 31;
        int t = (loc >> 7) & 15;
        int kc = loc >> 11;
        int oc0 = t * 16 + (l >> 2);
        int p0 = kc * 8 + (l & 3);
        float2 a  = *(const float2*)&lw[(size_t)oc0 * K + 2 * p0];
        float2 b  = *(const float2*)&lw[(size_t)(oc0 + 8) * K + 2 * p0];
        float2 cc = *(const float2*)&lw[(size_t)oc0 * K + 2 * (p0 + 4)];
        float2 d  = *(const float2*)&lw[(size_t)(oc0 + 8) * K + 2 * (p0 + 4)];
        uint4 pk;
        pk.x = packh2(a.x, a.y);
        pk.y = packh2(b.x, b.y);
        pk.z = packh2(cc.x, cc.y);
        pk.w = packh2(d.x, d.y);
        ((uint4*)g_lwh)[idx] = pk;
    } else if (bx < 4576) {
        // ---- x -> packed half2, 4 pixels per thread (vectorized) ----
        int idx4 = (bx - 736) * 256 + tid;   // 983040 total
        int lvl, off4, N;
        if (idx4 < 524288)      { lvl = 0; off4 = 0;      N = 16384; }
        else if (idx4 < 786432) { lvl = 1; off4 = 524288; N = 4096;  }
        else if (idx4 < 917504) { lvl = 2; off4 = 786432; N = 1024;  }
        else                    { lvl = 3; off4 = 917504; N = 256;   }
        const float* x = lvl == 0 ? x0 : lvl == 1 ? x1 : lvl == 2 ? x2 : x3;
        int i2 = (idx4 - off4) * 4;
        int p = i2 / N;
        int n = i2 - p * N;                 // multiple of 4
        const float4 a = *(const float4*)&x[(size_t)(2 * p) * N + n];
        const float4 b = *(const float4*)&x[(size_t)(2 * p + 1) * N + n];
        uint4 pk;
        pk.x = packh2(a.x, b.x);
        pk.y = packh2(a.y, b.y);
        pk.z = packh2(a.z, b.z);
        pk.w = packh2(a.w, b.w);
        *(uint4*)&g_xh[(size_t)idx4 * 4] = pk;
    } else {
        // ---- init g_lat levels 1-3 with broadcast bias (for RED.ADD) ----
        int idx4 = (bx - 4576) * 256 + tid;  // 344064 total float4s
        int lvl, off4, N;
        if (idx4 < 262144)      { lvl = 1; off4 = 0;      N = 4096; }
        else if (idx4 < 327680) { lvl = 2; off4 = 262144; N = 1024; }
        else                    { lvl = 3; off4 = 327680; N = 256;  }
        constexpr int LATOFF[4] = {0, 4194304, 5242880, 5505024};
        int loc = idx4 - off4;
        int n4 = N >> 2;
        int c = loc / n4;
        float bv = lb[lvl * 256 + c];
        ((float4*)(g_lat + LATOFF[lvl]))[loc] = make_float4(bv, bv, bv, bv);
    }
}

// ---------------- lateral 1x1 conv, ALL levels + split-K (RED.ADD) --------
__global__ __launch_bounds__(256, 2)
void lat_mma_all(const float* __restrict__ lb)
{
    constexpr int SEG[4]    = {0, 128, 192, 224};
    constexpr int NB[4]     = {128, 32, 8, 2};
    constexpr int NS[4]     = {16384, 4096, 1024, 256};
    constexpr int LWOFF[4]  = {0, 32768, 98304, 229376};
    constexpr int XOFF[4]   = {0, 2097152, 3145728, 3670016};
    constexpr int LATOFF[4] = {0, 4194304, 5242880, 5505024};

    __shared__ uint32_t sB[2][16 * 136];
    const int tid = threadIdx.x;
    const int wid = tid >> 5, lid = tid & 31;
    const int g = lid >> 2, tig = lid & 3;
    const int warp_m = wid & 3, warp_n = wid >> 2;

    const int bx = blockIdx.x;
    const int lvl = bx >= SEG[3] ? 3 : bx >= SEG[2] ? 2 : bx >= SEG[1] ? 1 : 0;
    const int sub = bx - SEG[lvl];
    const int nb = sub & (NB[lvl] - 1);
    const int z = sub / NB[lvl];
    const int N = NS[lvl];
    const int n0 = nb * 128;
    const int my = blockIdx.y;

    const uint32_t* xh = g_xh + XOFF[lvl];
    const uint4* lw4 = (const uint4*)(g_lwh + LWOFF[lvl]);
    const uint32_t sbase = smem_u32(&sB[0][0]);
    const bool addb = (lvl == 0);
    float* out = g_lat + LATOFF[lvl];

    float c[2][8][4];
#pragma unroll
    for (int mt = 0; mt < 2; mt++)
#pragma unroll
        for (int nt = 0; nt < 8; nt++)
#pragma unroll
            for (int q = 0; q < 4; q++) c[mt][nt][q] = 0.f;

    auto fill = [&](int ch, int b) {
        const int p0 = z * 128 + ch * 16;
#pragma unroll
        for (int e = tid; e < 512; e += 256) {
            int row = e >> 5, cw = e & 31;
            const uint32_t* src = xh + (size_t)(p0 + row) * N + n0 + cw * 4;
            uint32_t dst = sbase + (uint32_t)(b * 2176 + row * 136 + cw * 4) * 4u;
            CP_ASYNC16(dst, src);
        }
    };

    fill(0, 0);
    CP_COMMIT();
    CP_WAIT0();
    __syncthreads();

    for (int ch = 0; ch < 8; ch++) {
        const int cur = ch & 1;
        if (ch < 7) {
            fill(ch + 1, cur ^ 1);
            CP_COMMIT();
        }
        const uint32_t* s = &sB[cur][0];
#pragma unroll
        for (int ks = 0; ks < 2; ks++) {
            const int kc = z * 16 + ch * 2 + ks;
            uint32_t a[2][4];
#pragma unroll
            for (int mt = 0; mt < 2; mt++) {
                int t = my * 8 + warp_m * 2 + mt;
                uint4 av = lw4[(kc * 16 + t) * 32 + lid];
                a[mt][0] = av.x; a[mt][1] = av.y;
                a[mt][2] = av.z; a[mt][3] = av.w;
            }
            const int base_lo = (ks * 8 + tig) * 136;
            const int base_hi = base_lo + 4 * 136;
#pragma unroll
            for (int nt = 0; nt < 8; nt++) {
                int n = warp_n * 64 + nt * 8 + g;
                mma16h(c[0][nt], a[0], s[base_lo + n], s[base_hi + n]);
                mma16h(c[1][nt], a[1], s[base_lo + n], s[base_hi + n]);
            }
        }
        if (ch < 7) CP_WAIT0();
        __syncthreads();
    }

#pragma unroll
    for (int mt = 0; mt < 2; mt++) {
        int oc_lo = (my * 8 + warp_m * 2 + mt) * 16 + g;
        int oc_hi = oc_lo + 8;
        float blo = addb ? lb[oc_lo] : 0.f;
        float bhi = addb ? lb[oc_hi] : 0.f;
#pragma unroll
        for (int nt = 0; nt < 8; nt++) {
            int col = n0 + warp_n * 64 + nt * 8 + 2 * tig;
            float* plo = out + (size_t)oc_lo * N + col;
            float* phi = out + (size_t)oc_hi * N + col;
            if (addb) {
                *(float2*)plo = make_float2(c[mt][nt][0] + blo, c[mt][nt][1] + blo);
                *(float2*)phi = make_float2(c[mt][nt][2] + bhi, c[mt][nt][3] + bhi);
            } else {
                atomicAdd(plo, c[mt][nt][0]);
                atomicAdd(plo + 1, c[mt][nt][1]);
                atomicAdd(phi, c[mt][nt][2]);
                atomicAdd(phi + 1, c[mt][nt][3]);
            }
        }
    }
}

// ---------------- fused top-down + half2 convert, 4 px / thread -----------
__global__ void upcvt_all()
{
    constexpr int LATOFF[4] = {0, 4194304, 5242880, 5505024};
    int idx4 = blockIdx.x * 256 + threadIdx.x;
    if (idx4 >= 696320) return;
    int lvl, off4, lhw;
    if (idx4 < 524288)      { lvl = 0; off4 = 0;      lhw = 14; }
    else if (idx4 < 655360) { lvl = 1; off4 = 524288; lhw = 12; }
    else if (idx4 < 688128) { lvl = 2; off4 = 655360; lhw = 10; }
    else                    { lvl = 3; off4 = 688128; lhw = 8;  }
    int local = (idx4 - off4) * 4;   // half2 index within level
    int HW = 1 << lhw;
    int c = local >> lhw;
    int i = local & (HW - 1);
    int lw = lhw >> 1;
    int W = 1 << lw;
    int y = i >> lw, x = i & (W - 1);   // x multiple of 4
    float v0[4], v1[4];
    {
        const float* l0 = g_lat + LATOFF[lvl];
        const float4 a = *(const float4*)&l0[(size_t)(2 * c) * HW + i];
        const float4 b = *(const float4*)&l0[(size_t)(2 * c + 1) * HW + i];
        v0[0] = a.x; v0[1] = a.y; v0[2] = a.z; v0[3] = a.w;
        v1[0] = b.x; v1[1] = b.y; v1[2] = b.z; v1[3] = b.w;
    }
#pragma unroll
    for (int j = 1; j < 4; j++) {
        if (lvl + j > 3) break;
        int lj_ = lvl + j;
        int sh = j;
        int Wj = W >> sh;
        int HWj = HW >> (2 * sh);
        const float* lj = g_lat + LATOFF[lj_];
        int ybase = (y >> sh) * Wj;
        if (sh == 1) {
            int e = ybase + (x >> 1);
            float2 a = *(const float2*)&lj[(size_t)(2 * c) * HWj + e];
            float2 b = *(const float2*)&lj[(size_t)(2 * c + 1) * HWj + e];
            v0[0] += a.x; v0[1] += a.x; v0[2] += a.y; v0[3] += a.y;
            v1[0] += b.x; v1[1] += b.x; v1[2] += b.y; v1[3] += b.y;
        } else {
            int e = ybase + (x >> sh);
            float a = lj[(size_t)(2 * c) * HWj + e];
            float b = lj[(size_t)(2 * c + 1) * HWj + e];
#pragma unroll
            for (int t = 0; t < 4; t++) { v0[t] += a; v1[t] += b; }
        }
    }
    uint4 pk;
    pk.x = packh2(v0[0], v1[0]);
    pk.y = packh2(v0[1], v1[1]);
    pk.z = packh2(v0[2], v1[2]);
    pk.w = packh2(v0[3], v1[3]);
    *(uint4*)&g_lath[(size_t)idx4 * 4] = pk;
}

// ---------------- stage 1: per-tap GEMM T_j = W_j * lat (no shift) --------
// grid (170, 18): bx -> (lvl, 128-px block); by -> (j = by>>1, oc half)
__global__ __launch_bounds__(256, 2)
void t_gemm()
{
    constexpr int HS[4]      = {16384, 4096, 1024, 256};    // HW per level
    constexpr int LATHOFF[4] = {0, 2097152, 2621440, 2752512};
    constexpr int TOFF[4]    = {0, 18874368, 23592960, 24772608};
    constexpr int TSTART[5]  = {0, 128, 160, 168, 170};

    __shared__ uint32_t sB[2][16 * 136];
    const int tid = threadIdx.x;
    const int wid = tid >> 5, lid = tid & 31;
    const int g = lid >> 2, tig = lid & 3;
    const int warp_m = wid & 3, warp_n = wid >> 2;

    int bx = blockIdx.x;
    int lvl = 0;
    if (bx >= TSTART[1]) lvl = (bx >= TSTART[3]) ? 3 : ((bx >= TSTART[2]) ? 2 : 1);
    const int tb = bx - TSTART[lvl];
    const int HW = HS[lvl];
    const int px0 = tb * 128;
    const int j = blockIdx.y >> 1;
    const int oh = blockIdx.y & 1;

    const uint32_t* lath = g_lath + LATHOFF[lvl];
    const uint4* wtj = (const uint4*)g_wt + lvl * 73728 + j * 8192;
    const uint32_t sbase = smem_u32(&sB[0][0]);

    float c[2][8][4];
#pragma unroll
    for (int mt = 0; mt < 2; mt++)
#pragma unroll
        for (int nt = 0; nt < 8; nt++)
#pragma unroll
            for (int q = 0; q < 4; q++) c[mt][nt][q] = 0.f;

    auto fill = [&](int ch, int b) {
        const int p0 = ch * 16;
#pragma unroll
        for (int e = tid; e < 512; e += 256) {
            int row = e >> 5, cw = e & 31;
            const uint32_t* src = lath + (size_t)(p0 + row) * HW + px0 + cw * 4;
            uint32_t dst = sbase + (uint32_t)(b * 2176 + row * 136 + cw * 4) * 4u;
            CP_ASYNC16(dst, src);
        }
    };

    fill(0, 0);
    CP_COMMIT();
    CP_WAIT0();
    __syncthreads();

    for (int ch = 0; ch < 8; ch++) {
        const int cur = ch & 1;
        if (ch < 7) {
            fill(ch + 1, cur ^ 1);
            CP_COMMIT();
        }
        const uint32_t* s = &sB[cur][0];
#pragma unroll
        for (int ks = 0; ks < 2; ks++) {
            const int kc = ch * 2 + ks;
            uint32_t a[2][4];
#pragma unroll
            for (int mt = 0; mt < 2; mt++) {
                int t = oh * 8 + warp_m * 2 + mt;
                uint4 av = wtj[(kc * 16 + t) * 32 + lid];
                a[mt][0] = av.x; a[mt][1] = av.y;
                a[mt][2] = av.z; a[mt][3] = av.w;
            }
            const int base_lo = (ks * 8 + tig) * 136;
            const int base_hi = base_lo + 4 * 136;
#pragma unroll
            for (int nt = 0; nt < 8; nt++) {
                int n = warp_n * 64 + nt * 8 + g;
                mma16h(c[0][nt], a[0], s[base_lo + n], s[base_hi + n]);
                mma16h(c[1][nt], a[1], s[base_lo + n], s[base_hi + n]);
            }
        }
        if (ch < 7) CP_WAIT0();
        __syncthreads();
    }

    // ---- epilogue: stage C tile through smem, write coalesced rows ----
    uint32_t* s_c = &sB[0][0];   // 4352 u32 available; need 64*65 = 4160
    const int HW2 = HW >> 1;
    uint32_t* Tb = g_T + TOFF[lvl] + (size_t)(j * 256 + oh * 128) * HW2 + (px0 >> 1);
#pragma unroll
    for (int half = 0; half < 2; half++) {
        __syncthreads();
        if ((warp_m >> 1) == half) {
            const int wm = warp_m & 1;
#pragma unroll
            for (int mt = 0; mt < 2; mt++) {
                int m_lo = wm * 32 + mt * 16 + g;
                int m_hi = m_lo + 8;
#pragma unroll
                for (int nt = 0; nt < 8; nt++) {
                    int cu = warp_n * 32 + nt * 4 + tig;
                    s_c[m_lo * 65 + cu] = packh2(c[mt][nt][0], c[mt][nt][1]);
                    s_c[m_hi * 65 + cu] = packh2(c[mt][nt][2], c[mt][nt][3]);
                }
            }
        }
        __syncthreads();
        const int row = tid >> 2, part = tid & 3;
        uint32_t* dst = Tb + (size_t)(half * 64 + row) * HW2 + part * 16;
        const uint32_t* srcp = &s_c[row * 65 + part * 16];
#pragma unroll
        for (int u = 0; u < 4; u++)
            ((uint4*)dst)[u] = make_uint4(srcp[4 * u], srcp[4 * u + 1],
                                          srcp[4 * u + 2], srcp[4 * u + 3]);
    }
}

// ---------------- stage 2 v4: aligned uint2 loads + shfl halo -------------
__global__ __launch_bounds__(256)
void sum_bn4(const float* __restrict__ bias4,
             const float* __restrict__ bng4, const float* __restrict__ bnb4,
             const float* __restrict__ bnm4, const float* __restrict__ bnv4)
{
    constexpr int INVK[5][9] = {
        {0, 1, 2, 3, 4, 5, 6, 7, 8},
        {1, 2, 5, 0, 4, 8, 3, 6, 7},
        {2, 5, 8, 1, 4, 7, 0, 3, 6},
        {5, 8, 7, 2, 4, 6, 1, 0, 3},
        {8, 7, 6, 5, 4, 3, 2, 1, 0}};
    constexpr int HSW[4]    = {128, 64, 32, 16};
    constexpr int TOFF[4]   = {0, 18874368, 23592960, 24772608};
    constexpr int FEOFFH[4] = {0, 10485760, 13107200, 13762560};
    constexpr int CSTART[5] = {0, 2048, 3072, 3584, 3840};
    constexpr int RBS[4]    = {3, 2, 1, 0};   // log2 row-blocks per oc

    const int wid = threadIdx.x >> 5;
    const int lane = threadIdx.x & 31;

    int bx = blockIdx.x;
    int lvl = 0;
    if (bx >= CSTART[1]) lvl = (bx >= CSTART[3]) ? 3 : ((bx >= CSTART[2]) ? 2 : 1);
    const int local = bx - CSTART[lvl];
    const int rbs = RBS[lvl];
    const int oc = local >> rbs;
    const int rblk = local & ((1 << rbs) - 1);
    const int W = HSW[lvl], H = W;
    const int W2 = W >> 1;
    const int HW2 = (W * W) >> 1;
    const int y0 = (rblk * 8 + wid) * 2;
    const int c = 2 * lane;               // u32 column of first output pair
    const int x0 = 4 * lane;              // first output pixel (float)
    const bool active = x0 < W;
    const bool has_right = (x0 + 4) < W;  // right halo from lane+1 valid

    const uint32_t* Tb = g_T + TOFF[lvl] + (size_t)oc * HW2;

    float acc[5][2][4];
#pragma unroll
    for (int r = 0; r < 5; r++)
#pragma unroll
        for (int p = 0; p < 2; p++)
#pragma unroll
            for (int t = 0; t < 4; t++) acc[r][p][t] = 0.f;

#pragma unroll
    for (int j = 0; j < 9; j++) {
        const uint32_t* base = Tb + (size_t)j * 256 * HW2;
        float f[4][6];
#pragma unroll
        for (int d = 0; d < 4; d++) {
            int yr = y0 - 1 + d;
            bool rok = active && ((unsigned)yr < (unsigned)H);
            uint2 v = make_uint2(0u, 0u);
            if (rok) v = *(const uint2*)&base[(size_t)yr * W2 + c];
            float2 a = __half22float2(*(const __half2*)&v.x);
            float2 b = __half22float2(*(const __half2*)&v.y);
            f[d][1] = a.x; f[d][2] = a.y; f[d][3] = b.x; f[d][4] = b.y;
            float lf = __shfl_up_sync(0xffffffffu, b.y, 1);
            float rt = __shfl_down_sync(0xffffffffu, a.x, 1);
            f[d][0] = (lane == 0) ? 0.f : lf;
            f[d][5] = has_right ? rt : 0.f;
        }
#pragma unroll
        for (int r = 0; r < 5; r++) {
            const int k = INVK[r][j];
            const int ky = k / 3, kx = k % 3;
#pragma unroll
            for (int t = 0; t < 4; t++) {
                acc[r][0][t] += f[ky][t + kx];
                acc[r][1][t] += f[ky + 1][t + kx];
            }
        }
    }

    // epilogue: bias + BN + relu -> feas (uint2 x 2 rows) + fsum warp-atomic
    const float bv = bias4[lvl * 256 + oc];
    uint32_t* fpb = g_feash + FEOFFH[lvl];
    float fs = 0.f;
#pragma unroll
    for (int r = 0; r < 5; r++) {
        int bi = lvl * 1280 + r * 256 + oc;
        float sc = bng4[bi] * rsqrtf(bnv4[bi] + BN_EPS);
        float sh = bnb4[bi] + (bv - bnm4[bi]) * sc;
        if (active) {
#pragma unroll
            for (int p = 0; p < 2; p++) {
                float v0 = fmaxf(fmaf(acc[r][p][0], sc, sh), 0.f);
                float v1 = fmaxf(fmaf(acc[r][p][1], sc, sh), 0.f);
                float v2 = fmaxf(fmaf(acc[r][p][2], sc, sh), 0.f);
                float v3 = fmaxf(fmaf(acc[r][p][3], sc, sh), 0.f);
                uint2 pk;
                pk.x = packh2(v0, v1);
                pk.y = packh2(v2, v3);
                *(uint2*)&fpb[(size_t)(r * 256 + oc) * HW2 + (size_t)(y0 + p) * W2 + c] = pk;
                fs += v0 + v1 + v2 + v3;
            }
        }
    }
#pragma unroll
    for (int o = 16; o > 0; o >>= 1) fs += __shfl_down_sync(0xffffffffu, fs, o);
    if (lane == 0) atomicAdd(&g_fsum[lvl * 256 + oc], fs);
}

// ---------------- fea_z: grid (8, 4), warp-reduced (coalesced) ------------
__global__ void fz_all(const float* __restrict__ fcw4, const float* __restrict__ fcb4)
{
    constexpr int HWs[4] = {16384, 4096, 1024, 256};
    int lvl = blockIdx.y;
    const float* fcw = fcw4 + lvl * 32768;
    const float* fcb = fcb4 + lvl * 128;
    float inv = 1.f / (float)HWs[lvl];
    int g = threadIdx.x >> 4;
    int lane = threadIdx.x & 15;
    int d = blockIdx.x * 16 + g;
    float s = 0.f;
    for (int c = lane; c < 256; c += 16)
        s += fcw[d * 256 + c] * (g_fsum[lvl * 256 + c] * inv);
#pragma unroll
    for (int o = 8; o > 0; o >>= 1) s += __shfl_down_sync(0xffffffffu, s, o, 16);
    if (lane == 0) g_fz[lvl * 128 + d] = s + fcb[d];
}

// ---------------- att: grid (32, 4), lanes over d (coalesced) -------------
__global__ void att_all(const float* __restrict__ fcsw4, const float* __restrict__ fcsb4)
{
    int lvl = blockIdx.y;
    const float* fcsw = fcsw4 + lvl * 163840;
    const float* fcsb = fcsb4 + lvl * 1280;
    __shared__ float fz[128];
    if (threadIdx.x < 128) fz[threadIdx.x] = g_fz[lvl * 128 + threadIdx.x];
    __syncthreads();
    int cl = threadIdx.x >> 5;
    int lane = threadIdx.x & 31;
    int c = blockIdx.x * 8 + cl;
    float lg[5];
#pragma unroll
    for (int m = 0; m < 5; m++) {
        float s = 0.f;
#pragma unroll
        for (int i = 0; i < 4; i++) {
            int d = lane + i * 32;
            s += fz[d] * fcsw[((m * 256 + c) * 128) + d];
        }
#pragma unroll
        for (int o = 16; o > 0; o >>= 1) s += __shfl_down_sync(0xffffffffu, s, o);
        lg[m] = s;
    }
    if (lane == 0) {
        float mx = -1e30f;
#pragma unroll
        for (int m = 0; m < 5; m++) {
            lg[m] += fcsb[m * 256 + c];
            mx = fmaxf(mx, lg[m]);
        }
        float den = 0.f;
#pragma unroll
        for (int m = 0; m < 5; m++) { lg[m] = expf(lg[m] - mx); den += lg[m]; }
        float inv = 1.f / den;
#pragma unroll
        for (int m = 0; m < 5; m++) g_att[lvl * 1280 + m * 256 + c] = lg[m] * inv;
    }
}

// ---------------- out: all levels, 8 px / thread --------------------------
__global__ void wsum_all(float* __restrict__ out)
{
    constexpr int FEOFFH[4] = {0, 10485760, 13107200, 13762560};
    constexpr int LATOFF[4] = {0, 4194304, 5242880, 5505024};
    constexpr int HWs[4]    = {16384, 4096, 1024, 256};
    constexpr int BSTART[5] = {0, 2048, 2560, 2688, 2720};
    int b = blockIdx.x;
    int lvl = 0;
    if (b >= BSTART[1]) lvl = (b >= BSTART[3]) ? 3 : ((b >= BSTART[2]) ? 2 : 1);
    int i8 = (b - BSTART[lvl]) * 256 + threadIdx.x;
    int HW = HWs[lvl];
    int hw8 = HW >> 3;
    int c = i8 / hw8;
    int p = i8 - c * hw8;
    const uint32_t* f = g_feash + FEOFFH[lvl];
    const float* att = g_att + lvl * 1280;
    float acc[8];
#pragma unroll
    for (int t = 0; t < 8; t++) acc[t] = 0.f;
#pragma unroll
    for (int m = 0; m < 5; m++) {
        float a = att[m * 256 + c];
        uint4 raw = *(const uint4*)&f[(size_t)(m * 256 + c) * (HW >> 1) + p * 4];
        float2 v0 = __half22float2(*(const __half2*)&raw.x);
        float2 v1 = __half22float2(*(const __half2*)&raw.y);
        float2 v2 = __half22float2(*(const __half2*)&raw.z);
        float2 v3 = __half22float2(*(const __half2*)&raw.w);
        acc[0] = fmaf(a, v0.x, acc[0]); acc[1] = fmaf(a, v0.y, acc[1]);
        acc[2] = fmaf(a, v1.x, acc[2]); acc[3] = fmaf(a, v1.y, acc[3]);
        acc[4] = fmaf(a, v2.x, acc[4]); acc[5] = fmaf(a, v2.y, acc[5]);
        acc[6] = fmaf(a, v3.x, acc[6]); acc[7] = fmaf(a, v3.y, acc[7]);
    }
    float* op = out + LATOFF[lvl] + (size_t)i8 * 8;
    *(float4*)op = make_float4(acc[0], acc[1], acc[2], acc[3]);
    *(float4*)(op + 4) = make_float4(acc[4], acc[5], acc[6], acc[7]);
}

// ---------------- launch ----------------
extern "C" void kernel_launch(void* const* d_in, const int* in_sizes, int n_in,
                              void* d_out, int out_size)
{
    const float *x[4], *lw[4];
    if (in_sizes[1] == 65536) {           // interleaved: x0,lw0,x1,lw1,...
        for (int i = 0; i < 4; i++) {
            x[i]  = (const float*)d_in[2 * i];
            lw[i] = (const float*)d_in[2 * i + 1];
        }
    } else {                              // grouped: x0..x3, lw0..lw3
        for (int i = 0; i < 4; i++) {
            x[i]  = (const float*)d_in[i];
            lw[i] = (const float*)d_in[4 + i];
        }
    }
    const float* lb   = (const float*)d_in[8];
    const float* aacw = (const float*)d_in[9];
    const float* aacb = (const float*)d_in[10];
    const float* bng  = (const float*)d_in[11];
    const float* bnb  = (const float*)d_in[12];
    const float* bnm  = (const float*)d_in[13];
    const float* bnv  = (const float*)d_in[14];
    const float* fcw  = (const float*)d_in[15];
    const float* fcb  = (const float*)d_in[16];
    const float* fcsw = (const float*)d_in[17];
    const float* fcsb = (const float*)d_in[18];
    float* out = (float*)d_out;

    // 0) fused prep: conv wt | lat wt | x convert | g_lat bias init
    prep_all<<<5920, 256>>>(aacw, lw[0], lw[1], lw[2], lw[3],
                            x[0], x[1], x[2], x[3], lb);

    // 1) lateral 1x1 convs, all levels; split-K via RED.ADD (no reduce pass)
    lat_mma_all<<<dim3(240, 2), 256>>>(lb);

    // 2) fused top-down pathway + half2 convert (4 px / thread)
    upcvt_all<<<2720, 256>>>();

    // 3) stage 1: nine per-tap GEMMs (coalesced smem-staged epilogue)
    t_gemm<<<dim3(170, 18), 256>>>();

    // 4) stage 2 v4: shfl-halo 9-tap shift-sum + BN + relu + fused fsum
    sum_bn4<<<3840, 256>>>(aacb, bng, bnb, bnm, bnv);

    // 5) SK fusion tail (coalesced split kernels)
    fz_all<<<dim3(8, 4), 256>>>(fcw, fcb);
    att_all<<<dim3(32, 4), 256>>>(fcsw, fcsb);
    wsum_all<<<2720, 256>>>(out);

    (void)n_in; (void)out_size;
}